// round 1
// baseline (speedup 1.0000x reference)
#include <cuda_runtime.h>
#include <cstdint>

// ---------------------------------------------------------------------------
// Problem constants
// ---------------------------------------------------------------------------
constexpr int E  = 8;
constexpr int Bb = 16384;
constexpr int Nn = 64;
constexpr int H  = 512;
constexpr int A  = 8;
constexpr int D  = 64;
constexpr int AD = A * D;          // 512

// ---------------------------------------------------------------------------
// Scratch layout (single __device__ global; offsets in floats)
// ---------------------------------------------------------------------------
constexpr long long SZ_SUMS = 2LL * E * 16 * Nn;        // partial sums+sumsq, 16 chunks
constexpr long long SZ_MU   = E * Nn;
constexpr long long SZ_RSTD = E * Nn;
constexpr long long SZ_WP   = (long long)E * Nn * H;    // BN-folded encoder weights
constexpr long long SZ_BP   = (long long)E * H;
constexpr long long SZ_WK   = (long long)H * AD;
constexpr long long SZ_WV   = (long long)H * AD;
constexpr long long SZ_WSEL = (long long)H * AD;
constexpr long long SZ_WOUT = (long long)H * 128;
constexpr long long SZ_BOUT = 128;
constexpr long long SZ_ENCS = (long long)E * Bb * H;
constexpr long long SZ_KEYS = (long long)E * Bb * AD;
constexpr long long SZ_VALS = (long long)E * Bb * AD;
constexpr long long SZ_PRE  = (long long)Bb * H;
constexpr long long SZ_SEL  = (long long)Bb * AD;
constexpr long long SZ_X    = (long long)Bb * H;
constexpr long long SZ_TMP  = (long long)Bb * 128;

constexpr long long OFF_SUMS = 0;
constexpr long long OFF_MU   = OFF_SUMS + SZ_SUMS;
constexpr long long OFF_RSTD = OFF_MU   + SZ_MU;
constexpr long long OFF_WP   = OFF_RSTD + SZ_RSTD;
constexpr long long OFF_BP   = OFF_WP   + SZ_WP;
constexpr long long OFF_WK   = OFF_BP   + SZ_BP;
constexpr long long OFF_WV   = OFF_WK   + SZ_WK;
constexpr long long OFF_WSEL = OFF_WV   + SZ_WV;
constexpr long long OFF_WOUT = OFF_WSEL + SZ_WSEL;
constexpr long long OFF_BOUT = OFF_WOUT + SZ_WOUT;
constexpr long long OFF_ENCS = OFF_BOUT + SZ_BOUT;
constexpr long long OFF_KEYS = OFF_ENCS + SZ_ENCS;
constexpr long long OFF_VALS = OFF_KEYS + SZ_KEYS;
constexpr long long OFF_PRE  = OFF_VALS + SZ_VALS;
constexpr long long OFF_SEL  = OFF_PRE  + SZ_PRE;
constexpr long long OFF_X    = OFF_SEL  + SZ_SEL;
constexpr long long OFF_TMP  = OFF_X    + SZ_X;
constexpr long long SCRATCH_TOTAL = OFF_TMP + SZ_TMP;   // ~229.7M floats (~919 MB)

__device__ float g_scratch[SCRATCH_TOTAL];

// ---------------------------------------------------------------------------
// BatchNorm partial sums: grid (16 chunks, E), 256 threads.
// Each block handles 1024 rows of states[e]; thread t owns column n = t%64.
// Writes partials[(e*16+c)*64+n] and +8192 for sumsq.  Deterministic (no atomics).
// ---------------------------------------------------------------------------
__global__ void bn_partial_kernel(const float* __restrict__ states, float* __restrict__ partial)
{
    int c = blockIdx.x;           // chunk 0..15
    int e = blockIdx.y;
    int t = threadIdx.x;
    int n = t & 63;
    int r0 = t >> 6;              // 0..3

    const float* sp = states + (long long)e * Bb * Nn;
    long long b = (long long)c * 1024 + r0;

    float s1 = 0.f, s2 = 0.f;
    #pragma unroll 4
    for (int it = 0; it < 256; ++it) {
        float v = sp[(b + (long long)it * 4) * Nn + n];
        s1 += v;
        s2 += v * v;
    }

    __shared__ float sh1[256], sh2[256];
    sh1[t] = s1; sh2[t] = s2;
    __syncthreads();
    if (t < 64) {
        float a1 = sh1[t] + sh1[t + 64] + sh1[t + 128] + sh1[t + 192];
        float a2 = sh2[t] + sh2[t + 64] + sh2[t + 128] + sh2[t + 192];
        long long base = ((long long)e * 16 + c) * 64 + t;
        partial[base]                 = a1;
        partial[8192 + base]          = a2;
    }
}

// mu / rstd from partials. 512 threads.
__global__ void bn_final_kernel(const float* __restrict__ partial,
                                float* __restrict__ mu, float* __restrict__ rstd)
{
    int idx = blockIdx.x * blockDim.x + threadIdx.x;   // e*64+n
    if (idx >= E * Nn) return;
    int e = idx >> 6, n = idx & 63;
    float s1 = 0.f, s2 = 0.f;
    for (int c = 0; c < 16; ++c) {
        long long base = ((long long)e * 16 + c) * 64 + n;
        s1 += partial[base];
        s2 += partial[8192 + base];
    }
    float m = s1 * (1.f / Bb);
    float var = s2 * (1.f / Bb) - m * m;
    mu[idx] = m;
    rstd[idx] = rsqrtf(var + 1e-5f);
}

// Fold BN into encoder weights: W'[e][n][h] = rstd*W, b'[e][h] = b - sum_n mu*rstd*W.
__global__ void fold_enc_kernel(const float* __restrict__ W_enc, const float* __restrict__ b_enc,
                                const float* __restrict__ mu, const float* __restrict__ rstd,
                                float* __restrict__ Wp, float* __restrict__ bp)
{
    int idx = blockIdx.x * blockDim.x + threadIdx.x;   // e*512+h
    if (idx >= E * H) return;
    int e = idx >> 9, h = idx & 511;
    float bacc = b_enc[(long long)e * H + h];
    const float* We = W_enc + (long long)e * Nn * H;
    float* Wpe = Wp + (long long)e * Nn * H;
    #pragma unroll 8
    for (int n = 0; n < Nn; ++n) {
        float w  = We[(long long)n * H + h];
        float wn = rstd[e * Nn + n] * w;
        Wpe[(long long)n * H + h] = wn;
        bacc -= mu[e * Nn + n] * wn;
    }
    bp[(long long)e * H + h] = bacc;
}

// Pack per-head weights [A,H,d] -> [H, A*d].
__global__ void pack_heads_kernel(const float* __restrict__ Wk, const float* __restrict__ Wsel,
                                  const float* __restrict__ Wv,
                                  float* __restrict__ pk, float* __restrict__ psel,
                                  float* __restrict__ pv)
{
    int idx = blockIdx.x * blockDim.x + threadIdx.x;   // over H*AD = 262144
    if (idx >= H * AD) return;
    int h = idx >> 9;
    int col = idx & 511;
    int a = col >> 6, dd = col & 63;
    long long src = ((long long)a * H + h) * D + dd;
    pk[idx]   = Wk[src];
    psel[idx] = Wsel[src];
    pv[idx]   = Wv[src];
}

// Pack [W_mean | W_logstd] -> [H,128], and biases -> [128].
__global__ void pack_out_kernel(const float* __restrict__ W_mean, const float* __restrict__ W_logstd,
                                const float* __restrict__ b_mean, const float* __restrict__ b_logstd,
                                float* __restrict__ Wout, float* __restrict__ bout)
{
    int idx = blockIdx.x * blockDim.x + threadIdx.x;   // over H*128 = 65536
    if (idx < H * 128) {
        int h = idx >> 7, j = idx & 127;
        Wout[idx] = (j < 64) ? W_mean[(long long)h * 64 + j]
                             : W_logstd[(long long)h * 64 + (j - 64)];
    }
    if (blockIdx.x == 0 && threadIdx.x < 128) {
        int j = threadIdx.x;
        bout[j] = (j < 64) ? b_mean[j] : b_logstd[j - 64];
    }
}

// ---------------------------------------------------------------------------
// Generic batched fp32 GEMM: C = epi(A[M,K] @ B[K,N] + bias[N])
// 128x128 tile, TK=16, 256 threads, 8x8 per-thread micro-tile.
// Requires M%128==0, N%128==0, K%16==0 (true for all stages here).
// EPI: 0 = none, 1 = leaky_relu(0.01), 2 = relu
// ---------------------------------------------------------------------------
template <int EPI>
__global__ __launch_bounds__(256, 2)
void gemm128_kernel(const float* __restrict__ Ag, const float* __restrict__ Bg,
                    const float* __restrict__ biasg, float* __restrict__ Cg,
                    int M, int N, int K,
                    long long sA, long long sB, long long sC, long long sBias)
{
    const int bz = blockIdx.z;
    const float* Ab = Ag + (long long)bz * sA;
    const float* Bm = Bg + (long long)bz * sB;
    float* C = Cg + (long long)bz * sC;
    const float* bias = biasg ? (biasg + (long long)bz * sBias) : nullptr;

    __shared__ float As[16][132];   // transposed A tile (k-major), padded
    __shared__ float Bs[16][128];

    const int t  = threadIdx.x;
    const int tx = t & 15;
    const int ty = t >> 4;
    const int m0 = blockIdx.y * 128;
    const int n0 = blockIdx.x * 128;

    float acc[8][8];
    #pragma unroll
    for (int i = 0; i < 8; ++i)
        #pragma unroll
        for (int j = 0; j < 8; ++j) acc[i][j] = 0.f;

    for (int k0 = 0; k0 < K; k0 += 16) {
        // A tile: 128 rows x 16 k, float4 along k, store transposed
        #pragma unroll
        for (int i = 0; i < 2; ++i) {
            int lin = t + i * 256;              // 0..511
            int m = lin >> 2;
            int kq = lin & 3;
            float4 v = *reinterpret_cast<const float4*>(
                &Ab[(long long)(m0 + m) * K + k0 + kq * 4]);
            As[kq * 4 + 0][m] = v.x;
            As[kq * 4 + 1][m] = v.y;
            As[kq * 4 + 2][m] = v.z;
            As[kq * 4 + 3][m] = v.w;
        }
        // B tile: 16 k x 128 n, float4 along n
        #pragma unroll
        for (int i = 0; i < 2; ++i) {
            int lin = t + i * 256;
            int k = lin >> 5;
            int nq = lin & 31;
            *reinterpret_cast<float4*>(&Bs[k][nq * 4]) =
                *reinterpret_cast<const float4*>(&Bm[(long long)(k0 + k) * N + n0 + nq * 4]);
        }
        __syncthreads();

        #pragma unroll
        for (int kk = 0; kk < 16; ++kk) {
            float4 b0 = *reinterpret_cast<float4*>(&Bs[kk][tx * 8]);
            float4 b1 = *reinterpret_cast<float4*>(&Bs[kk][tx * 8 + 4]);
            float av[8];
            #pragma unroll
            for (int i = 0; i < 8; ++i) av[i] = As[kk][ty * 8 + i];
            #pragma unroll
            for (int i = 0; i < 8; ++i) {
                acc[i][0] += av[i] * b0.x;
                acc[i][1] += av[i] * b0.y;
                acc[i][2] += av[i] * b0.z;
                acc[i][3] += av[i] * b0.w;
                acc[i][4] += av[i] * b1.x;
                acc[i][5] += av[i] * b1.y;
                acc[i][6] += av[i] * b1.z;
                acc[i][7] += av[i] * b1.w;
            }
        }
        __syncthreads();
    }

    float bb[8];
    #pragma unroll
    for (int j = 0; j < 8; ++j) bb[j] = bias ? bias[n0 + tx * 8 + j] : 0.f;

    #pragma unroll
    for (int i = 0; i < 8; ++i) {
        long long row = m0 + ty * 8 + i;
        float v[8];
        #pragma unroll
        for (int j = 0; j < 8; ++j) {
            float x = acc[i][j] + bb[j];
            if (EPI == 1) x = (x >= 0.f) ? x : 0.01f * x;
            if (EPI == 2) x = fmaxf(x, 0.f);
            v[j] = x;
        }
        float4* cp = reinterpret_cast<float4*>(&C[row * (long long)N + n0 + tx * 8]);
        cp[0] = make_float4(v[0], v[1], v[2], v[3]);
        cp[1] = make_float4(v[4], v[5], v[6], v[7]);
    }
}

// ---------------------------------------------------------------------------
// Attention: one block per b, one warp per head a.
// logits[e] = (sel . keys[e]) / 8; softmax over E=8; attn = sum_e w*vals[e].
// keys/vals layout: [e][b][a*64+dd]; sel: [b][a*64+dd]; writes actor_in[b][a*64+dd].
// ---------------------------------------------------------------------------
__global__ void attn_kernel(const float* __restrict__ keys, const float* __restrict__ vals,
                            const float* __restrict__ sel, float* __restrict__ actor_in)
{
    const int b = blockIdx.x;
    const int a = threadIdx.x >> 5;
    const int lane = threadIdx.x & 31;
    const int colbase = a * 64 + lane * 2;

    const float2 s2 = *reinterpret_cast<const float2*>(&sel[(long long)b * AD + colbase]);

    float v0[E], v1[E], logit[E];
    #pragma unroll
    for (int e = 0; e < E; ++e) {
        long long off = ((long long)e * Bb + b) * AD + colbase;
        float2 k2 = *reinterpret_cast<const float2*>(&keys[off]);
        float2 vv = *reinterpret_cast<const float2*>(&vals[off]);
        v0[e] = vv.x; v1[e] = vv.y;
        float p = s2.x * k2.x + s2.y * k2.y;
        #pragma unroll
        for (int o = 16; o >= 1; o >>= 1) p += __shfl_xor_sync(0xffffffffu, p, o);
        logit[e] = p * 0.125f;   // / sqrt(64)
    }

    float mx = logit[0];
    #pragma unroll
    for (int e = 1; e < E; ++e) mx = fmaxf(mx, logit[e]);
    float den = 0.f;
    float w[E];
    #pragma unroll
    for (int e = 0; e < E; ++e) { w[e] = __expf(logit[e] - mx); den += w[e]; }
    float inv = 1.f / den;

    float a0 = 0.f, a1 = 0.f;
    #pragma unroll
    for (int e = 0; e < E; ++e) {
        float we = w[e] * inv;
        a0 += we * v0[e];
        a1 += we * v1[e];
    }
    *reinterpret_cast<float2*>(&actor_in[(long long)b * AD + colbase]) = make_float2(a0, a1);
}

// Split tmp [B,128] -> mean [B,64] and clipped log_std [B,64] regions of d_out.
__global__ void split_out_kernel(const float* __restrict__ tmp, float* __restrict__ out)
{
    long long idx = (long long)blockIdx.x * blockDim.x + threadIdx.x;
    if (idx >= (long long)Bb * 128) return;
    long long b = idx >> 7;
    int j = (int)(idx & 127);
    float v = tmp[idx];
    if (j < 64) {
        out[b * 64 + j] = v;
    } else {
        v = fminf(fmaxf(v, -20.f), 2.f);
        out[(long long)Bb * 64 + b * 64 + (j - 64)] = v;
    }
}

// ---------------------------------------------------------------------------
// Launch
// ---------------------------------------------------------------------------
extern "C" void kernel_launch(void* const* d_in, const int* in_sizes, int n_in,
                              void* d_out, int out_size)
{
    float* S = nullptr;
    cudaGetSymbolAddress((void**)&S, g_scratch);

    const float* states      = (const float*)d_in[0];
    const float* pre_actions = (const float*)d_in[1];
    const float* W_enc       = (const float*)d_in[2];
    const float* b_enc       = (const float*)d_in[3];
    const float* W_pre       = (const float*)d_in[4];
    const float* b_pre       = (const float*)d_in[5];
    const float* Wk          = (const float*)d_in[6];
    const float* Wsel        = (const float*)d_in[7];
    const float* Wv          = (const float*)d_in[8];
    const float* bv          = (const float*)d_in[9];
    const float* W_actor     = (const float*)d_in[10];
    const float* b_actor     = (const float*)d_in[11];
    const float* W_mean      = (const float*)d_in[12];
    const float* b_mean      = (const float*)d_in[13];
    const float* W_logstd    = (const float*)d_in[14];
    const float* b_logstd    = (const float*)d_in[15];

    float* out = (float*)d_out;
    float* actor_in = out + 2LL * Bb * Nn;   // third output region, reused as activation

    // BatchNorm stats + weight folding + packing (all tiny)
    bn_partial_kernel<<<dim3(16, E), 256>>>(states, S + OFF_SUMS);
    bn_final_kernel<<<2, 256>>>(S + OFF_SUMS, S + OFF_MU, S + OFF_RSTD);
    fold_enc_kernel<<<16, 256>>>(W_enc, b_enc, S + OFF_MU, S + OFF_RSTD,
                                 S + OFF_WP, S + OFF_BP);
    pack_heads_kernel<<<1024, 256>>>(Wk, Wsel, Wv, S + OFF_WK, S + OFF_WSEL, S + OFF_WV);
    pack_out_kernel<<<256, 256>>>(W_mean, W_logstd, b_mean, b_logstd,
                                  S + OFF_WOUT, S + OFF_BOUT);

    // Stage B: encs[e] = leaky(states[e] @ W'[e] + b'[e])     [16384,64]x[64,512] x8
    gemm128_kernel<1><<<dim3(AD / 128, Bb / 128, E), 256>>>(
        states, S + OFF_WP, S + OFF_BP, S + OFF_ENCS,
        Bb, H, Nn,
        (long long)Bb * Nn, (long long)Nn * H, (long long)Bb * H, (long long)H);

    // Stage C: keys[e] = encs[e] @ Wk_flat                    [16384,512]x[512,512] x8
    gemm128_kernel<0><<<dim3(AD / 128, Bb / 128, E), 256>>>(
        S + OFF_ENCS, S + OFF_WK, nullptr, S + OFF_KEYS,
        Bb, AD, H,
        (long long)Bb * H, 0LL, (long long)Bb * AD, 0LL);

    // Stage D: vals[e] = leaky(encs[e] @ Wv_flat + bv_flat)
    gemm128_kernel<1><<<dim3(AD / 128, Bb / 128, E), 256>>>(
        S + OFF_ENCS, S + OFF_WV, bv, S + OFF_VALS,
        Bb, AD, H,
        (long long)Bb * H, 0LL, (long long)Bb * AD, 0LL);

    // Stage E: pre = leaky(pre_actions @ W_pre + b_pre)       [16384,512]x[512,512]
    gemm128_kernel<1><<<dim3(H / 128, Bb / 128, 1), 256>>>(
        pre_actions, W_pre, b_pre, S + OFF_PRE,
        Bb, H, H, 0LL, 0LL, 0LL, 0LL);

    // Stage F: sel = pre @ Wsel_flat
    gemm128_kernel<0><<<dim3(AD / 128, Bb / 128, 1), 256>>>(
        S + OFF_PRE, S + OFF_WSEL, nullptr, S + OFF_SEL,
        Bb, AD, H, 0LL, 0LL, 0LL, 0LL);

    // Attention + head concat -> actor_in (written directly into d_out)
    attn_kernel<<<Bb, 256>>>(S + OFF_KEYS, S + OFF_VALS, S + OFF_SEL, actor_in);

    // Stage H: x = relu(actor_in @ W_actor + b_actor)
    gemm128_kernel<2><<<dim3(H / 128, Bb / 128, 1), 256>>>(
        actor_in, W_actor, b_actor, S + OFF_X,
        Bb, H, H, 0LL, 0LL, 0LL, 0LL);

    // Stage I: tmp = x @ [W_mean|W_logstd] + [b_mean|b_logstd]   [16384,512]x[512,128]
    gemm128_kernel<0><<<dim3(1, Bb / 128, 1), 256>>>(
        S + OFF_X, S + OFF_WOUT, S + OFF_BOUT, S + OFF_TMP,
        Bb, 128, H, 0LL, 0LL, 0LL, 0LL);

    // Split into mean / clipped log_std
    split_out_kernel<<<(Bb * 128 + 255) / 256, 256>>>(S + OFF_TMP, out);
}

// round 3
// speedup vs baseline: 1.3749x; 1.3749x over previous
#include <cuda_runtime.h>
#include <cuda_bf16.h>
#include <cstdint>

// ---------------------------------------------------------------------------
// Problem constants
// ---------------------------------------------------------------------------
constexpr int E  = 8;
constexpr int Bb = 16384;
constexpr int Nn = 64;
constexpr int H  = 512;
constexpr int AD = 512;            // A*D

// ---------------------------------------------------------------------------
// Scratch layout (words of 4 bytes)
// ---------------------------------------------------------------------------
constexpr long long OFF_SUMS  = 0;                         // 2*E*16*64 = 16384
constexpr long long OFF_MU    = OFF_SUMS  + 16384;         // 512
constexpr long long OFF_RSTD  = OFF_MU    + 512;           // 512
constexpr long long OFF_BP    = OFF_RSTD  + 512;           // E*H = 4096
constexpr long long OFF_KVB   = OFF_BP    + 4096;          // 1024
constexpr long long OFF_BOUT  = OFF_KVB   + 1024;          // 128
constexpr long long OFF_EHI   = OFF_BOUT  + 128;           // E*512*32 = 131072
constexpr long long OFF_ELO   = OFF_EHI   + 131072;
constexpr long long OFF_KVHI  = OFF_ELO   + 131072;        // 1024*256 = 262144
constexpr long long OFF_KVLO  = OFF_KVHI  + 262144;
constexpr long long OFF_SELHI = OFF_KVLO  + 262144;        // 512*256 = 131072
constexpr long long OFF_SELLO = OFF_SELHI + 131072;
constexpr long long OFF_PREHI = OFF_SELLO + 131072;
constexpr long long OFF_PRELO = OFF_PREHI + 131072;
constexpr long long OFF_ACTHI = OFF_PRELO + 131072;
constexpr long long OFF_ACTLO = OFF_ACTHI + 131072;
constexpr long long OFF_OHI   = OFF_ACTLO + 131072;        // 128*256 = 32768
constexpr long long OFF_OLO   = OFF_OHI   + 32768;
constexpr long long OFF_ENCS  = OFF_OLO   + 32768;         // E*B*H   = 67108864
constexpr long long OFF_KV    = OFF_ENCS  + 67108864LL;    // E*B*1024= 134217728
constexpr long long OFF_PRE   = OFF_KV    + 134217728LL;   // B*H
constexpr long long OFF_SEL   = OFF_PRE   + 8388608LL;
constexpr long long OFF_X     = OFF_SEL   + 8388608LL;
constexpr long long SCRATCH_TOTAL = OFF_X + 8388608LL;     // ~912 MB

__device__ __align__(256) float g_scratch[SCRATCH_TOTAL];

// ---------------------------------------------------------------------------
// Helpers
// ---------------------------------------------------------------------------
__device__ __forceinline__ uint32_t pack_split(float x, float y, uint32_t& lo)
{
    __nv_bfloat16 hx = __float2bfloat16_rn(x);
    __nv_bfloat16 hy = __float2bfloat16_rn(y);
    float rx = x - __bfloat162float(hx);
    float ry = y - __bfloat162float(hy);
    __nv_bfloat16 lx = __float2bfloat16_rn(rx);
    __nv_bfloat16 ly = __float2bfloat16_rn(ry);
    lo = (uint32_t)__bfloat16_as_ushort(lx) | ((uint32_t)__bfloat16_as_ushort(ly) << 16);
    return (uint32_t)__bfloat16_as_ushort(hx) | ((uint32_t)__bfloat16_as_ushort(hy) << 16);
}

#define MMA_BF16(d, a, b0v, b1v)                                              \
    asm volatile("mma.sync.aligned.m16n8k16.row.col.f32.bf16.bf16.f32 "       \
                 "{%0,%1,%2,%3}, {%4,%5,%6,%7}, {%8,%9}, {%0,%1,%2,%3};"      \
                 : "+f"(d[0]), "+f"(d[1]), "+f"(d[2]), "+f"(d[3])             \
                 : "r"(a[0]), "r"(a[1]), "r"(a[2]), "r"(a[3]),                \
                   "r"(b0v), "r"(b1v))

#define LDSM_X4(r, addr)                                                      \
    asm volatile("ldmatrix.sync.aligned.m8n8.x4.shared.b16 {%0,%1,%2,%3}, [%4];" \
                 : "=r"(r[0]), "=r"(r[1]), "=r"(r[2]), "=r"(r[3]) : "r"(addr))

// ---------------------------------------------------------------------------
// BatchNorm stats
// ---------------------------------------------------------------------------
__global__ void bn_partial_kernel(const float* __restrict__ states, float* __restrict__ partial)
{
    int c = blockIdx.x, e = blockIdx.y, t = threadIdx.x;
    int n = t & 63, r0 = t >> 6;
    const float* sp = states + (long long)e * Bb * Nn;
    long long b = (long long)c * 1024 + r0;
    float s1 = 0.f, s2 = 0.f;
    #pragma unroll 4
    for (int it = 0; it < 256; ++it) {
        float v = sp[(b + (long long)it * 4) * Nn + n];
        s1 += v; s2 += v * v;
    }
    __shared__ float sh1[256], sh2[256];
    sh1[t] = s1; sh2[t] = s2;
    __syncthreads();
    if (t < 64) {
        float a1 = sh1[t] + sh1[t + 64] + sh1[t + 128] + sh1[t + 192];
        float a2 = sh2[t] + sh2[t + 64] + sh2[t + 128] + sh2[t + 192];
        long long base = ((long long)e * 16 + c) * 64 + t;
        partial[base] = a1;
        partial[8192 + base] = a2;
    }
}

__global__ void bn_final_kernel(const float* __restrict__ partial,
                                float* __restrict__ mu, float* __restrict__ rstd)
{
    int idx = blockIdx.x * blockDim.x + threadIdx.x;
    if (idx >= E * Nn) return;
    int e = idx >> 6, n = idx & 63;
    float s1 = 0.f, s2 = 0.f;
    for (int c = 0; c < 16; ++c) {
        long long base = ((long long)e * 16 + c) * 64 + n;
        s1 += partial[base];
        s2 += partial[8192 + base];
    }
    float m = s1 * (1.f / Bb);
    float var = s2 * (1.f / Bb) - m * m;
    mu[idx] = m;
    rstd[idx] = rsqrtf(var + 1e-5f);
}

// ---------------------------------------------------------------------------
// Weight prep: fold BN, pack heads, split into bf16 hi/lo planes
// stored n-major with k in pairs: plane[n][K/2] (uint32 = 2 bf16).
// ---------------------------------------------------------------------------
__global__ void enc_fold_split_kernel(const float* __restrict__ W_enc, const float* __restrict__ b_enc,
                                      const float* __restrict__ mu, const float* __restrict__ rstd,
                                      uint32_t* __restrict__ hi, uint32_t* __restrict__ lo,
                                      float* __restrict__ bp)
{
    int idx = blockIdx.x * blockDim.x + threadIdx.x;   // e*512+h
    if (idx >= E * H) return;
    int e = idx >> 9, h = idx & 511;
    float bacc = b_enc[idx];
    #pragma unroll
    for (int p = 0; p < 32; ++p) {
        int k = 2 * p;
        float w0 = rstd[e * 64 + k]     * W_enc[((long long)e * 64 + k) * H + h];
        float w1 = rstd[e * 64 + k + 1] * W_enc[((long long)e * 64 + k + 1) * H + h];
        bacc -= mu[e * 64 + k] * w0 + mu[e * 64 + k + 1] * w1;
        uint32_t l; uint32_t hh = pack_split(w0, w1, l);
        hi[(long long)idx * 32 + p] = hh;
        lo[(long long)idx * 32 + p] = l;
    }
    bp[idx] = bacc;
}

__global__ void kv_pack_split_kernel(const float* __restrict__ Wk, const float* __restrict__ Wv,
                                     const float* __restrict__ bv,
                                     uint32_t* __restrict__ hi, uint32_t* __restrict__ lo,
                                     float* __restrict__ kvbias)
{
    int n = blockIdx.x * blockDim.x + threadIdx.x;     // 0..1023
    if (n >= 1024) return;
    bool isv = n >= 512;
    int a = (n & 511) >> 6, dd = n & 63;
    const float* W = isv ? Wv : Wk;
    for (int p = 0; p < 256; ++p) {
        int k = 2 * p;
        float w0 = W[((long long)a * H + k) * 64 + dd];
        float w1 = W[((long long)a * H + k + 1) * 64 + dd];
        uint32_t l; uint32_t hh = pack_split(w0, w1, l);
        hi[(long long)n * 256 + p] = hh;
        lo[(long long)n * 256 + p] = l;
    }
    kvbias[n] = isv ? bv[n - 512] : 0.f;
}

__global__ void sel_pack_split_kernel(const float* __restrict__ Wsel,
                                      uint32_t* __restrict__ hi, uint32_t* __restrict__ lo)
{
    int n = blockIdx.x * blockDim.x + threadIdx.x;     // 0..511
    if (n >= 512) return;
    int a = n >> 6, dd = n & 63;
    for (int p = 0; p < 256; ++p) {
        int k = 2 * p;
        float w0 = Wsel[((long long)a * H + k) * 64 + dd];
        float w1 = Wsel[((long long)a * H + k + 1) * 64 + dd];
        uint32_t l; uint32_t hh = pack_split(w0, w1, l);
        hi[(long long)n * 256 + p] = hh;
        lo[(long long)n * 256 + p] = l;
    }
}

__global__ void mat_split_kernel(const float* __restrict__ W,   // [512][512] row-major k x n
                                 uint32_t* __restrict__ hi, uint32_t* __restrict__ lo)
{
    int n = blockIdx.x * blockDim.x + threadIdx.x;
    if (n >= 512) return;
    for (int p = 0; p < 256; ++p) {
        float w0 = W[(long long)(2 * p) * 512 + n];
        float w1 = W[(long long)(2 * p + 1) * 512 + n];
        uint32_t l; uint32_t hh = pack_split(w0, w1, l);
        hi[(long long)n * 256 + p] = hh;
        lo[(long long)n * 256 + p] = l;
    }
}

__global__ void out_pack_split_kernel(const float* __restrict__ W_mean, const float* __restrict__ W_logstd,
                                      const float* __restrict__ b_mean, const float* __restrict__ b_logstd,
                                      uint32_t* __restrict__ hi, uint32_t* __restrict__ lo,
                                      float* __restrict__ bout)
{
    int n = blockIdx.x * blockDim.x + threadIdx.x;     // 0..127
    if (n >= 128) return;
    const float* W = (n < 64) ? W_mean : W_logstd;
    int j = n & 63;
    for (int p = 0; p < 256; ++p) {
        float w0 = W[(long long)(2 * p) * 64 + j];
        float w1 = W[(long long)(2 * p + 1) * 64 + j];
        uint32_t l; uint32_t hh = pack_split(w0, w1, l);
        hi[(long long)n * 256 + p] = hh;
        lo[(long long)n * 256 + p] = l;
    }
    bout[n] = (n < 64) ? b_mean[j] : b_logstd[j];
}

// ---------------------------------------------------------------------------
// Split-bf16 tensor-core GEMM: C = epi(A[M,K] @ W[K,N] + bias)
// A fp32 in gmem (split hi/lo on the fly); W pre-split planes [N][K/2].
// 128x128 CTA tile, 8 warps x (64x32), double-buffered smem.
// EPI: 0 none, 1 leaky, 2 relu, 3 kv-mode (leaky iff col>=512), 4 out-split+clip
// ---------------------------------------------------------------------------
constexpr int SMW = 1536;   // words per 128x12 plane
constexpr int BUFW = 4 * SMW;

template <int EPI>
__global__ __launch_bounds__(256, 1)
void mma_gemm_kernel(const float* __restrict__ Ag,
                     const uint32_t* __restrict__ BhiG,
                     const uint32_t* __restrict__ BloG,
                     const float* __restrict__ biasg,
                     float* __restrict__ Cg,
                     int M, int N, int K,
                     long long sA, long long sBw, long long sBias, long long sC)
{
    __shared__ uint32_t sm[2 * BUFW];   // 48 KB

    const int bz = blockIdx.z;
    const float* Ab = Ag + bz * sA;
    const uint32_t* BhB = BhiG + bz * sBw;
    const uint32_t* BlB = BloG + bz * sBw;
    const float* bias = biasg ? (biasg + bz * sBias) : nullptr;
    float* C = Cg + bz * sC;

    const int t = threadIdx.x;
    const int lane = t & 31;
    const int warp = t >> 5;
    const int wm = warp >> 2;           // 0..1
    const int wn = warp & 3;            // 0..3
    const int m0 = blockIdx.y * 128;
    const int n0 = blockIdx.x * 128;
    const int Kw = K >> 1;

    // staging roles
    const int am = t >> 1;              // A row 0..127
    const int ak = t & 1;               // k half
    const int bpl = t >> 7;             // B plane 0=hi 1=lo
    const int bn = t & 127;             // B row (n)

    float acc[4][4][4];
    #pragma unroll
    for (int i = 0; i < 4; ++i)
        #pragma unroll
        for (int j = 0; j < 4; ++j)
            #pragma unroll
            for (int q = 0; q < 4; ++q) acc[i][j][q] = 0.f;

    const uint32_t sbase = (uint32_t)__cvta_generic_to_shared(sm);
    const uint32_t aoff = (((uint32_t)(wm * 64 + (lane & 15)) * 12 + (lane >> 4) * 4)) * 4;
    const uint32_t boff = (((uint32_t)(wn * 32 + (lane & 7) + ((lane >> 4) & 1) * 8) * 12
                            + ((lane >> 3) & 1) * 4)) * 4;

    const float* aptr = Ab + (long long)(m0 + am) * K + ak * 8;
    const uint32_t* bptr = (bpl ? BlB : BhB) + (long long)(n0 + bn) * Kw;
    uint32_t* aS_h = sm + am * 12 + ak * 4;                 // + buf*BUFW
    uint32_t* aS_l = aS_h + SMW;
    uint32_t* bS = sm + (2 + bpl) * SMW + bn * 12;

    float4 av0, av1;
    uint4 bv0, bv1;

    av0 = *(const float4*)(aptr);
    av1 = *(const float4*)(aptr + 4);
    bv0 = *(const uint4*)(bptr);
    bv1 = *(const uint4*)(bptr + 4);

    auto store_smem = [&](int buf) {
        float v[8] = {av0.x, av0.y, av0.z, av0.w, av1.x, av1.y, av1.z, av1.w};
        uint32_t hi[4], lo[4];
        #pragma unroll
        for (int j = 0; j < 4; ++j) hi[j] = pack_split(v[2 * j], v[2 * j + 1], lo[j]);
        *(uint4*)(aS_h + buf * BUFW) = make_uint4(hi[0], hi[1], hi[2], hi[3]);
        *(uint4*)(aS_l + buf * BUFW) = make_uint4(lo[0], lo[1], lo[2], lo[3]);
        *(uint4*)(bS + buf * BUFW) = bv0;
        *(uint4*)(bS + buf * BUFW + 4) = bv1;
    };

    auto mma_step = [&](int buf) {
        const uint32_t b0 = sbase + buf * (BUFW * 4);
        uint32_t AH[4][4], AL[4][4], BH[2][4], BL[2][4];
        #pragma unroll
        for (int i = 0; i < 4; ++i) {
            LDSM_X4(AH[i], b0 + aoff + i * (16 * 12 * 4));
            LDSM_X4(AL[i], b0 + SMW * 4 + aoff + i * (16 * 12 * 4));
        }
        #pragma unroll
        for (int j = 0; j < 2; ++j) {
            LDSM_X4(BH[j], b0 + 2 * SMW * 4 + boff + j * (16 * 12 * 4));
            LDSM_X4(BL[j], b0 + 3 * SMW * 4 + boff + j * (16 * 12 * 4));
        }
        #pragma unroll
        for (int i = 0; i < 4; ++i)
            #pragma unroll
            for (int jj = 0; jj < 4; ++jj) {
                const int jm = jj >> 1, js = (jj & 1) * 2;
                MMA_BF16(acc[i][jj], AH[i], BH[jm][js], BH[jm][js + 1]);
                MMA_BF16(acc[i][jj], AH[i], BL[jm][js], BL[jm][js + 1]);
                MMA_BF16(acc[i][jj], AL[i], BH[jm][js], BH[jm][js + 1]);
            }
    };

    store_smem(0);
    __syncthreads();

    int buf = 0;
    for (int k0 = 16; k0 < K; k0 += 16) {
        av0 = *(const float4*)(aptr + k0);
        av1 = *(const float4*)(aptr + k0 + 4);
        bv0 = *(const uint4*)(bptr + (k0 >> 1));
        bv1 = *(const uint4*)(bptr + (k0 >> 1) + 4);
        mma_step(buf);
        store_smem(buf ^ 1);
        __syncthreads();
        buf ^= 1;
    }
    mma_step(buf);

    // epilogue
    const int g = lane >> 2, tq = lane & 3;
    #pragma unroll
    for (int i = 0; i < 4; ++i) {
        const int row = m0 + wm * 64 + i * 16 + g;
        #pragma unroll
        for (int jj = 0; jj < 4; ++jj) {
            const int col = n0 + wn * 32 + jj * 8 + tq * 2;
            float b0v = bias ? bias[col] : 0.f;
            float b1v = bias ? bias[col + 1] : 0.f;
            float v00 = acc[i][jj][0] + b0v, v01 = acc[i][jj][1] + b1v;
            float v10 = acc[i][jj][2] + b0v, v11 = acc[i][jj][3] + b1v;
            if (EPI == 1) {
                v00 = v00 >= 0.f ? v00 : 0.01f * v00;
                v01 = v01 >= 0.f ? v01 : 0.01f * v01;
                v10 = v10 >= 0.f ? v10 : 0.01f * v10;
                v11 = v11 >= 0.f ? v11 : 0.01f * v11;
            } else if (EPI == 2) {
                v00 = fmaxf(v00, 0.f); v01 = fmaxf(v01, 0.f);
                v10 = fmaxf(v10, 0.f); v11 = fmaxf(v11, 0.f);
            } else if (EPI == 3) {
                if (col >= 512) {
                    v00 = v00 >= 0.f ? v00 : 0.01f * v00;
                    v01 = v01 >= 0.f ? v01 : 0.01f * v01;
                    v10 = v10 >= 0.f ? v10 : 0.01f * v10;
                    v11 = v11 >= 0.f ? v11 : 0.01f * v11;
                }
            }
            if (EPI == 4) {
                const long long base2 = (long long)M * 64;
                float vv[4] = {v00, v01, v10, v11};
                int rr[4] = {row, row, row + 8, row + 8};
                int cc[4] = {col, col + 1, col, col + 1};
                #pragma unroll
                for (int q = 0; q < 4; ++q) {
                    if (cc[q] < 64) {
                        C[(long long)rr[q] * 64 + cc[q]] = vv[q];
                    } else {
                        float x = fminf(fmaxf(vv[q], -20.f), 2.f);
                        C[base2 + (long long)rr[q] * 64 + (cc[q] - 64)] = x;
                    }
                }
            } else {
                *(float2*)&C[(long long)row * N + col] = make_float2(v00, v01);
                *(float2*)&C[(long long)(row + 8) * N + col] = make_float2(v10, v11);
            }
        }
    }
}

// ---------------------------------------------------------------------------
// Attention over KV buffer [e][b][1024] (keys cols 0..511, vals 512..1023)
// ---------------------------------------------------------------------------
__global__ void attn_kernel(const float* __restrict__ KV, const float* __restrict__ sel,
                            float* __restrict__ actor_in)
{
    const int b = blockIdx.x;
    const int a = threadIdx.x >> 5;
    const int lane = threadIdx.x & 31;
    const int colbase = a * 64 + lane * 2;

    const float2 s2 = *reinterpret_cast<const float2*>(&sel[(long long)b * AD + colbase]);

    float v0[E], v1[E], logit[E];
    #pragma unroll
    for (int e = 0; e < E; ++e) {
        long long off = ((long long)e * Bb + b) * 1024 + colbase;
        float2 k2 = *reinterpret_cast<const float2*>(&KV[off]);
        float2 vv = *reinterpret_cast<const float2*>(&KV[off + 512]);
        v0[e] = vv.x; v1[e] = vv.y;
        float p = s2.x * k2.x + s2.y * k2.y;
        #pragma unroll
        for (int o = 16; o >= 1; o >>= 1) p += __shfl_xor_sync(0xffffffffu, p, o);
        logit[e] = p * 0.125f;
    }
    float mx = logit[0];
    #pragma unroll
    for (int e = 1; e < E; ++e) mx = fmaxf(mx, logit[e]);
    float den = 0.f, w[E];
    #pragma unroll
    for (int e = 0; e < E; ++e) { w[e] = __expf(logit[e] - mx); den += w[e]; }
    float inv = 1.f / den;
    float a0 = 0.f, a1 = 0.f;
    #pragma unroll
    for (int e = 0; e < E; ++e) {
        float we = w[e] * inv;
        a0 += we * v0[e];
        a1 += we * v1[e];
    }
    *reinterpret_cast<float2*>(&actor_in[(long long)b * AD + colbase]) = make_float2(a0, a1);
}

// ---------------------------------------------------------------------------
// Launch
// ---------------------------------------------------------------------------
extern "C" void kernel_launch(void* const* d_in, const int* in_sizes, int n_in,
                              void* d_out, int out_size)
{
    float* S = nullptr;
    cudaGetSymbolAddress((void**)&S, g_scratch);
    uint32_t* Su = (uint32_t*)S;

    const float* states      = (const float*)d_in[0];
    const float* pre_actions = (const float*)d_in[1];
    const float* W_enc       = (const float*)d_in[2];
    const float* b_enc       = (const float*)d_in[3];
    const float* W_pre       = (const float*)d_in[4];
    const float* b_pre       = (const float*)d_in[5];
    const float* Wk          = (const float*)d_in[6];
    const float* Wsel        = (const float*)d_in[7];
    const float* Wv          = (const float*)d_in[8];
    const float* bv          = (const float*)d_in[9];
    const float* W_actor     = (const float*)d_in[10];
    const float* b_actor     = (const float*)d_in[11];
    const float* W_mean      = (const float*)d_in[12];
    const float* b_mean      = (const float*)d_in[13];
    const float* W_logstd    = (const float*)d_in[14];
    const float* b_logstd    = (const float*)d_in[15];

    float* out = (float*)d_out;
    float* actor_in = out + 2LL * Bb * 64;   // third output region doubles as activation

    // ---- prep (tiny) ----
    bn_partial_kernel<<<dim3(16, E), 256>>>(states, S + OFF_SUMS);
    bn_final_kernel<<<2, 256>>>(S + OFF_SUMS, S + OFF_MU, S + OFF_RSTD);
    enc_fold_split_kernel<<<16, 256>>>(W_enc, b_enc, S + OFF_MU, S + OFF_RSTD,
                                       Su + OFF_EHI, Su + OFF_ELO, S + OFF_BP);
    kv_pack_split_kernel<<<4, 256>>>(Wk, Wv, bv, Su + OFF_KVHI, Su + OFF_KVLO, S + OFF_KVB);
    sel_pack_split_kernel<<<2, 256>>>(Wsel, Su + OFF_SELHI, Su + OFF_SELLO);
    mat_split_kernel<<<2, 256>>>(W_pre, Su + OFF_PREHI, Su + OFF_PRELO);
    mat_split_kernel<<<2, 256>>>(W_actor, Su + OFF_ACTHI, Su + OFF_ACTLO);
    out_pack_split_kernel<<<1, 128>>>(W_mean, W_logstd, b_mean, b_logstd,
                                      Su + OFF_OHI, Su + OFF_OLO, S + OFF_BOUT);

    // ---- encoder: encs[e] = leaky(states[e] @ Wenc'[e] + bp[e]) ----
    mma_gemm_kernel<1><<<dim3(4, 128, E), 256>>>(
        states, Su + OFF_EHI, Su + OFF_ELO, S + OFF_BP, S + OFF_ENCS,
        Bb, H, Nn,
        (long long)Bb * Nn, 512LL * 32, 512LL, (long long)Bb * H);

    // ---- fused keys|vals: KV[e] = encs[e] @ [Wk|Wv] (+bv, leaky on vals) ----
    mma_gemm_kernel<3><<<dim3(8, 128, E), 256>>>(
        S + OFF_ENCS, Su + OFF_KVHI, Su + OFF_KVLO, S + OFF_KVB, S + OFF_KV,
        Bb, 1024, H,
        (long long)Bb * H, 0LL, 0LL, (long long)Bb * 1024);

    // ---- pre = leaky(pre_actions @ W_pre + b_pre) ----
    mma_gemm_kernel<1><<<dim3(4, 128, 1), 256>>>(
        pre_actions, Su + OFF_PREHI, Su + OFF_PRELO, b_pre, S + OFF_PRE,
        Bb, H, H, 0LL, 0LL, 0LL, 0LL);

    // ---- sel = pre @ Wsel ----
    mma_gemm_kernel<0><<<dim3(4, 128, 1), 256>>>(
        S + OFF_PRE, Su + OFF_SELHI, Su + OFF_SELLO, nullptr, S + OFF_SEL,
        Bb, AD, H, 0LL, 0LL, 0LL, 0LL);

    // ---- attention -> actor_in (in d_out) ----
    attn_kernel<<<Bb, 256>>>(S + OFF_KV, S + OFF_SEL, actor_in);

    // ---- x = relu(actor_in @ W_actor + b_actor) ----
    mma_gemm_kernel<2><<<dim3(4, 128, 1), 256>>>(
        actor_in, Su + OFF_ACTHI, Su + OFF_ACTLO, b_actor, S + OFF_X,
        Bb, H, H, 0LL, 0LL, 0LL, 0LL);

    // ---- fused output GEMM: [mean | clip(logstd)] straight into d_out ----
    mma_gemm_kernel<4><<<dim3(1, 128, 1), 256>>>(
        S + OFF_X, Su + OFF_OHI, Su + OFF_OLO, S + OFF_BOUT, out,
        Bb, 128, H, 0LL, 0LL, 0LL, 0LL);
}

// round 4
// speedup vs baseline: 1.5461x; 1.1245x over previous
#include <cuda_runtime.h>
#include <cuda_bf16.h>
#include <cstdint>

// ---------------------------------------------------------------------------
// Problem constants
// ---------------------------------------------------------------------------
constexpr int E  = 8;
constexpr int Bb = 16384;
constexpr int Nn = 64;
constexpr int H  = 512;
constexpr int AD = 512;            // A*D

// ---------------------------------------------------------------------------
// Scratch layout (4-byte words)
// ---------------------------------------------------------------------------
constexpr long long OFF_SUMS  = 0;                          // 16384
constexpr long long OFF_MU    = OFF_SUMS  + 16384;          // 512
constexpr long long OFF_RSTD  = OFF_MU    + 512;            // 512
constexpr long long OFF_BP    = OFF_RSTD  + 512;            // 4096
constexpr long long OFF_KVB   = OFF_BP    + 4096;           // 1024
constexpr long long OFF_BOUT  = OFF_KVB   + 1024;           // 128
// weight planes
constexpr long long OFF_EHI   = OFF_BOUT  + 128;            // E*512*32 = 131072
constexpr long long OFF_ELO   = OFF_EHI   + 131072;
constexpr long long OFF_KVHI  = OFF_ELO   + 131072;         // 1024*256 = 262144
constexpr long long OFF_KVLO  = OFF_KVHI  + 262144;
constexpr long long OFF_SELHI = OFF_KVLO  + 262144;         // 512*256
constexpr long long OFF_SELLO = OFF_SELHI + 131072;
constexpr long long OFF_PREHI = OFF_SELLO + 131072;
constexpr long long OFF_PRELO = OFF_PREHI + 131072;
constexpr long long OFF_ACTHI = OFF_PRELO + 131072;
constexpr long long OFF_ACTLO = OFF_ACTHI + 131072;
constexpr long long OFF_OHI   = OFF_ACTLO + 131072;         // 128*256
constexpr long long OFF_OLO   = OFF_OHI   + 32768;
// activation planes / buffers
constexpr long long OFF_ENCH  = OFF_OLO   + 32768;          // E*B*256 = 33554432
constexpr long long OFF_ENCL  = OFF_ENCH  + 33554432LL;
constexpr long long OFF_KV    = OFF_ENCL  + 33554432LL;     // E*B*1024 fp32
constexpr long long OFF_PREH  = OFF_KV    + 134217728LL;    // B*256
constexpr long long OFF_PREL  = OFF_PREH  + 4194304LL;
constexpr long long OFF_SEL   = OFF_PREL  + 4194304LL;      // B*512 fp32
constexpr long long OFF_AINH  = OFF_SEL   + 8388608LL;      // B*256
constexpr long long OFF_AINL  = OFF_AINH  + 4194304LL;
constexpr long long OFF_XH    = OFF_AINL  + 4194304LL;      // B*256
constexpr long long OFF_XL    = OFF_XH    + 4194304LL;
constexpr long long SCRATCH_TOTAL = OFF_XL + 4194304LL;     // ~944 MB

__device__ __align__(256) float g_scratch[SCRATCH_TOTAL];

// ---------------------------------------------------------------------------
// Helpers
// ---------------------------------------------------------------------------
__device__ __forceinline__ uint32_t pack_split(float x, float y, uint32_t& lo)
{
    __nv_bfloat16 hx = __float2bfloat16_rn(x);
    __nv_bfloat16 hy = __float2bfloat16_rn(y);
    float rx = x - __bfloat162float(hx);
    float ry = y - __bfloat162float(hy);
    __nv_bfloat16 lx = __float2bfloat16_rn(rx);
    __nv_bfloat16 ly = __float2bfloat16_rn(ry);
    lo = (uint32_t)__bfloat16_as_ushort(lx) | ((uint32_t)__bfloat16_as_ushort(ly) << 16);
    return (uint32_t)__bfloat16_as_ushort(hx) | ((uint32_t)__bfloat16_as_ushort(hy) << 16);
}

#define MMA_BF16(d, a, b0v, b1v)                                              \
    asm volatile("mma.sync.aligned.m16n8k16.row.col.f32.bf16.bf16.f32 "       \
                 "{%0,%1,%2,%3}, {%4,%5,%6,%7}, {%8,%9}, {%0,%1,%2,%3};"      \
                 : "+f"(d[0]), "+f"(d[1]), "+f"(d[2]), "+f"(d[3])             \
                 : "r"(a[0]), "r"(a[1]), "r"(a[2]), "r"(a[3]),                \
                   "r"(b0v), "r"(b1v))

#define LDSM_X4(r, addr)                                                      \
    asm volatile("ldmatrix.sync.aligned.m8n8.x4.shared.b16 {%0,%1,%2,%3}, [%4];" \
                 : "=r"(r[0]), "=r"(r[1]), "=r"(r[2]), "=r"(r[3]) : "r"(addr))

// ---------------------------------------------------------------------------
// BatchNorm stats
// ---------------------------------------------------------------------------
__global__ void bn_partial_kernel(const float* __restrict__ states, float* __restrict__ partial)
{
    int c = blockIdx.x, e = blockIdx.y, t = threadIdx.x;
    int n = t & 63, r0 = t >> 6;
    const float* sp = states + (long long)e * Bb * Nn;
    long long b = (long long)c * 1024 + r0;
    float s1 = 0.f, s2 = 0.f;
    #pragma unroll 4
    for (int it = 0; it < 256; ++it) {
        float v = sp[(b + (long long)it * 4) * Nn + n];
        s1 += v; s2 += v * v;
    }
    __shared__ float sh1[256], sh2[256];
    sh1[t] = s1; sh2[t] = s2;
    __syncthreads();
    if (t < 64) {
        float a1 = sh1[t] + sh1[t + 64] + sh1[t + 128] + sh1[t + 192];
        float a2 = sh2[t] + sh2[t + 64] + sh2[t + 128] + sh2[t + 192];
        long long base = ((long long)e * 16 + c) * 64 + t;
        partial[base] = a1;
        partial[8192 + base] = a2;
    }
}

__global__ void bn_final_kernel(const float* __restrict__ partial,
                                float* __restrict__ mu, float* __restrict__ rstd)
{
    int idx = blockIdx.x * blockDim.x + threadIdx.x;
    if (idx >= E * Nn) return;
    int e = idx >> 6, n = idx & 63;
    float s1 = 0.f, s2 = 0.f;
    for (int c = 0; c < 16; ++c) {
        long long base = ((long long)e * 16 + c) * 64 + n;
        s1 += partial[base];
        s2 += partial[8192 + base];
    }
    float m = s1 * (1.f / Bb);
    float var = s2 * (1.f / Bb) - m * m;
    mu[idx] = m;
    rstd[idx] = rsqrtf(var + 1e-5f);
}

// ---------------------------------------------------------------------------
// Parallel weight-prep kernels (one thread per output element)
// ---------------------------------------------------------------------------
__global__ void enc_bias_kernel(const float* __restrict__ W_enc, const float* __restrict__ b_enc,
                                const float* __restrict__ mu, const float* __restrict__ rstd,
                                float* __restrict__ bp)
{
    int idx = blockIdx.x * blockDim.x + threadIdx.x;   // e*512+h
    if (idx >= E * H) return;
    int e = idx >> 9, h = idx & 511;
    float bacc = b_enc[idx];
    #pragma unroll 8
    for (int n = 0; n < Nn; ++n)
        bacc -= mu[e * 64 + n] * rstd[e * 64 + n] * W_enc[((long long)e * 64 + n) * H + h];
    bp[idx] = bacc;
}

__global__ void enc_split_kernel(const float* __restrict__ W_enc, const float* __restrict__ rstd,
                                 uint32_t* __restrict__ hi, uint32_t* __restrict__ lo)
{
    int idx = blockIdx.x * blockDim.x + threadIdx.x;   // E*H*32
    if (idx >= E * H * 32) return;
    int h = idx & 511;
    int rest = idx >> 9;
    int p = rest & 31;
    int e = rest >> 5;
    int k = 2 * p;
    float w0 = rstd[e * 64 + k]     * W_enc[((long long)e * 64 + k) * H + h];
    float w1 = rstd[e * 64 + k + 1] * W_enc[((long long)e * 64 + k + 1) * H + h];
    uint32_t l; uint32_t hh = pack_split(w0, w1, l);
    long long o = ((long long)e * 512 + h) * 32 + p;
    hi[o] = hh; lo[o] = l;
}

__global__ void kv_pack_kernel(const float* __restrict__ Wk, const float* __restrict__ Wv,
                               const float* __restrict__ bv,
                               uint32_t* __restrict__ hi, uint32_t* __restrict__ lo,
                               float* __restrict__ kvbias)
{
    int idx = blockIdx.x * blockDim.x + threadIdx.x;   // 1024*256
    if (idx >= 1024 * 256) return;
    int p = idx & 255, n = idx >> 8;
    bool isv = n >= 512;
    int a = (n & 511) >> 6, dd = n & 63;
    const float* W = isv ? Wv : Wk;
    int k = 2 * p;
    float w0 = W[((long long)a * H + k) * 64 + dd];
    float w1 = W[((long long)a * H + k + 1) * 64 + dd];
    uint32_t l; uint32_t hh = pack_split(w0, w1, l);
    hi[idx] = hh; lo[idx] = l;
    if (p == 0) kvbias[n] = isv ? bv[n - 512] : 0.f;
}

__global__ void sel_pack_kernel(const float* __restrict__ Wsel,
                                uint32_t* __restrict__ hi, uint32_t* __restrict__ lo)
{
    int idx = blockIdx.x * blockDim.x + threadIdx.x;   // 512*256
    if (idx >= 512 * 256) return;
    int p = idx & 255, n = idx >> 8;
    int a = n >> 6, dd = n & 63;
    int k = 2 * p;
    float w0 = Wsel[((long long)a * H + k) * 64 + dd];
    float w1 = Wsel[((long long)a * H + k + 1) * 64 + dd];
    uint32_t l; uint32_t hh = pack_split(w0, w1, l);
    hi[idx] = hh; lo[idx] = l;
}

__global__ void mat_split_kernel(const float* __restrict__ W,   // [512][512] k x n
                                 uint32_t* __restrict__ hi, uint32_t* __restrict__ lo)
{
    int idx = blockIdx.x * blockDim.x + threadIdx.x;   // 512*256
    if (idx >= 512 * 256) return;
    int p = idx & 255, n = idx >> 8;
    float w0 = W[(long long)(2 * p) * 512 + n];
    float w1 = W[(long long)(2 * p + 1) * 512 + n];
    uint32_t l; uint32_t hh = pack_split(w0, w1, l);
    hi[idx] = hh; lo[idx] = l;
}

__global__ void out_pack_kernel(const float* __restrict__ W_mean, const float* __restrict__ W_logstd,
                                const float* __restrict__ b_mean, const float* __restrict__ b_logstd,
                                uint32_t* __restrict__ hi, uint32_t* __restrict__ lo,
                                float* __restrict__ bout)
{
    int idx = blockIdx.x * blockDim.x + threadIdx.x;   // 128*256
    if (idx >= 128 * 256) return;
    int p = idx & 255, n = idx >> 8;
    const float* W = (n < 64) ? W_mean : W_logstd;
    int j = n & 63;
    float w0 = W[(long long)(2 * p) * 64 + j];
    float w1 = W[(long long)(2 * p + 1) * 64 + j];
    uint32_t l; uint32_t hh = pack_split(w0, w1, l);
    hi[idx] = hh; lo[idx] = l;
    if (p == 0) bout[n] = (n < 64) ? b_mean[j] : b_logstd[j];
}

// ---------------------------------------------------------------------------
// Split-bf16 tensor-core GEMM.
//   ASRC: 0 = A fp32 (split on the fly), 1 = A pre-split hi/lo planes [M][K/2]
//   ACT : 0 none, 1 leaky, 2 relu, 3 kv-mode (leaky iff col>=512), 4 out-split+clip
//   OUTM: 0 = fp32 C [M][N], 1 = hi/lo planes [M][N/2]
// 128x128 CTA tile, 8 warps x (64x32), double-buffered smem.
// ---------------------------------------------------------------------------
constexpr int SMW = 1536;   // words per 128x12 plane
constexpr int BUFW = 4 * SMW;

template <int ACT, int OUTM, int ASRC>
__global__ __launch_bounds__(256, 1)
void mma_gemm_kernel(const float* __restrict__ Af,
                     const uint32_t* __restrict__ AhiG, const uint32_t* __restrict__ AloG,
                     const uint32_t* __restrict__ BhiG, const uint32_t* __restrict__ BloG,
                     const float* __restrict__ biasg,
                     float* __restrict__ Cf,
                     uint32_t* __restrict__ ChiG, uint32_t* __restrict__ CloG,
                     int M, int N, int K,
                     long long sA, long long sBw, long long sBias, long long sC)
{
    __shared__ uint32_t sm[2 * BUFW];   // 48 KB

    const int bz = blockIdx.z;
    const float* Ab = (ASRC == 0) ? (Af + bz * sA) : nullptr;
    const uint32_t* AhB = (ASRC == 1) ? (AhiG + bz * sA) : nullptr;
    const uint32_t* AlB = (ASRC == 1) ? (AloG + bz * sA) : nullptr;
    const uint32_t* BhB = BhiG + bz * sBw;
    const uint32_t* BlB = BloG + bz * sBw;
    const float* bias = biasg ? (biasg + bz * sBias) : nullptr;
    float* C = Cf ? (Cf + bz * sC) : nullptr;
    uint32_t* Chi = ChiG ? (ChiG + bz * sC) : nullptr;
    uint32_t* Clo = CloG ? (CloG + bz * sC) : nullptr;

    const int t = threadIdx.x;
    const int lane = t & 31;
    const int warp = t >> 5;
    const int wm = warp >> 2;           // 0..1
    const int wn = warp & 3;            // 0..3
    const int m0 = blockIdx.y * 128;
    const int n0 = blockIdx.x * 128;
    const int Kw = K >> 1;

    // staging roles
    const int am = t >> 1;              // A row 0..127
    const int ak = t & 1;               // k half
    const int bpl = t >> 7;             // B plane 0=hi 1=lo
    const int bn = t & 127;             // B row (n)

    float acc[4][4][4];
    #pragma unroll
    for (int i = 0; i < 4; ++i)
        #pragma unroll
        for (int j = 0; j < 4; ++j)
            #pragma unroll
            for (int q = 0; q < 4; ++q) acc[i][j][q] = 0.f;

    const uint32_t sbase = (uint32_t)__cvta_generic_to_shared(sm);
    const uint32_t aoff = (((uint32_t)(wm * 64 + (lane & 15)) * 12 + (lane >> 4) * 4)) * 4;
    const uint32_t boff = (((uint32_t)(wn * 32 + (lane & 7) + ((lane >> 4) & 1) * 8) * 12
                            + ((lane >> 3) & 1) * 4)) * 4;

    const float* aptrf = (ASRC == 0) ? (Ab + (long long)(m0 + am) * K + ak * 8) : nullptr;
    const uint32_t* ahptr = (ASRC == 1) ? (AhB + (long long)(m0 + am) * Kw + ak * 4) : nullptr;
    const uint32_t* alptr = (ASRC == 1) ? (AlB + (long long)(m0 + am) * Kw + ak * 4) : nullptr;
    const uint32_t* bptr = (bpl ? BlB : BhB) + (long long)(n0 + bn) * Kw;

    uint32_t* aS_h = sm + am * 12 + ak * 4;                 // + buf*BUFW
    uint32_t* aS_l = aS_h + SMW;
    uint32_t* bS = sm + (2 + bpl) * SMW + bn * 12;

    float4 av0, av1;
    uint4 ahv, alv;
    uint4 bv0, bv1;

    // prologue: chunk 0
    if (ASRC == 0) {
        av0 = *(const float4*)(aptrf);
        av1 = *(const float4*)(aptrf + 4);
    } else {
        ahv = *(const uint4*)(ahptr);
        alv = *(const uint4*)(alptr);
    }
    bv0 = *(const uint4*)(bptr);
    bv1 = *(const uint4*)(bptr + 4);

    auto store_smem = [&](int buf) {
        if (ASRC == 0) {
            float v[8] = {av0.x, av0.y, av0.z, av0.w, av1.x, av1.y, av1.z, av1.w};
            uint32_t hi[4], lo[4];
            #pragma unroll
            for (int j = 0; j < 4; ++j) hi[j] = pack_split(v[2 * j], v[2 * j + 1], lo[j]);
            *(uint4*)(aS_h + buf * BUFW) = make_uint4(hi[0], hi[1], hi[2], hi[3]);
            *(uint4*)(aS_l + buf * BUFW) = make_uint4(lo[0], lo[1], lo[2], lo[3]);
        } else {
            *(uint4*)(aS_h + buf * BUFW) = ahv;
            *(uint4*)(aS_l + buf * BUFW) = alv;
        }
        *(uint4*)(bS + buf * BUFW) = bv0;
        *(uint4*)(bS + buf * BUFW + 4) = bv1;
    };

    auto mma_step = [&](int buf) {
        const uint32_t b0 = sbase + buf * (BUFW * 4);
        uint32_t AH[4][4], AL[4][4], BH[2][4], BL[2][4];
        #pragma unroll
        for (int i = 0; i < 4; ++i) {
            LDSM_X4(AH[i], b0 + aoff + i * (16 * 12 * 4));
            LDSM_X4(AL[i], b0 + SMW * 4 + aoff + i * (16 * 12 * 4));
        }
        #pragma unroll
        for (int j = 0; j < 2; ++j) {
            LDSM_X4(BH[j], b0 + 2 * SMW * 4 + boff + j * (16 * 12 * 4));
            LDSM_X4(BL[j], b0 + 3 * SMW * 4 + boff + j * (16 * 12 * 4));
        }
        #pragma unroll
        for (int i = 0; i < 4; ++i)
            #pragma unroll
            for (int jj = 0; jj < 4; ++jj) {
                const int jm = jj >> 1, js = (jj & 1) * 2;
                MMA_BF16(acc[i][jj], AH[i], BH[jm][js], BH[jm][js + 1]);
                MMA_BF16(acc[i][jj], AH[i], BL[jm][js], BL[jm][js + 1]);
                MMA_BF16(acc[i][jj], AL[i], BH[jm][js], BH[jm][js + 1]);
            }
    };

    store_smem(0);
    __syncthreads();

    int buf = 0;
    for (int k0 = 16; k0 < K; k0 += 16) {
        if (ASRC == 0) {
            av0 = *(const float4*)(aptrf + k0);
            av1 = *(const float4*)(aptrf + k0 + 4);
        } else {
            ahv = *(const uint4*)(ahptr + (k0 >> 1));
            alv = *(const uint4*)(alptr + (k0 >> 1));
        }
        bv0 = *(const uint4*)(bptr + (k0 >> 1));
        bv1 = *(const uint4*)(bptr + (k0 >> 1) + 4);
        mma_step(buf);
        store_smem(buf ^ 1);
        __syncthreads();
        buf ^= 1;
    }
    mma_step(buf);

    // epilogue
    const int g = lane >> 2, tq = lane & 3;
    const int Nw = N >> 1;
    #pragma unroll
    for (int i = 0; i < 4; ++i) {
        const int row = m0 + wm * 64 + i * 16 + g;
        #pragma unroll
        for (int jj = 0; jj < 4; ++jj) {
            const int col = n0 + wn * 32 + jj * 8 + tq * 2;
            float b0v = bias ? bias[col] : 0.f;
            float b1v = bias ? bias[col + 1] : 0.f;
            float v00 = acc[i][jj][0] + b0v, v01 = acc[i][jj][1] + b1v;
            float v10 = acc[i][jj][2] + b0v, v11 = acc[i][jj][3] + b1v;
            if (ACT == 1) {
                v00 = v00 >= 0.f ? v00 : 0.01f * v00;
                v01 = v01 >= 0.f ? v01 : 0.01f * v01;
                v10 = v10 >= 0.f ? v10 : 0.01f * v10;
                v11 = v11 >= 0.f ? v11 : 0.01f * v11;
            } else if (ACT == 2) {
                v00 = fmaxf(v00, 0.f); v01 = fmaxf(v01, 0.f);
                v10 = fmaxf(v10, 0.f); v11 = fmaxf(v11, 0.f);
            } else if (ACT == 3) {
                if (col >= 512) {
                    v00 = v00 >= 0.f ? v00 : 0.01f * v00;
                    v01 = v01 >= 0.f ? v01 : 0.01f * v01;
                    v10 = v10 >= 0.f ? v10 : 0.01f * v10;
                    v11 = v11 >= 0.f ? v11 : 0.01f * v11;
                }
            }
            if (ACT == 4) {
                // mean into C[r*64+j]; clipped logstd into C[M*64 + r*64 + (j-64)]
                const long long base2 = (long long)M * 64;
                float vv[4] = {v00, v01, v10, v11};
                int rr[4] = {row, row, row + 8, row + 8};
                int cc[4] = {col, col + 1, col, col + 1};
                #pragma unroll
                for (int q = 0; q < 4; ++q) {
                    if (cc[q] < 64) {
                        C[(long long)rr[q] * 64 + cc[q]] = vv[q];
                    } else {
                        float x = fminf(fmaxf(vv[q], -20.f), 2.f);
                        C[base2 + (long long)rr[q] * 64 + (cc[q] - 64)] = x;
                    }
                }
            } else if (OUTM == 1) {
                uint32_t l0, l1;
                uint32_t h0 = pack_split(v00, v01, l0);
                uint32_t h1 = pack_split(v10, v11, l1);
                Chi[(long long)row * Nw + (col >> 1)] = h0;
                Clo[(long long)row * Nw + (col >> 1)] = l0;
                Chi[(long long)(row + 8) * Nw + (col >> 1)] = h1;
                Clo[(long long)(row + 8) * Nw + (col >> 1)] = l1;
            } else {
                *(float2*)&C[(long long)row * N + col] = make_float2(v00, v01);
                *(float2*)&C[(long long)(row + 8) * N + col] = make_float2(v10, v11);
            }
        }
    }
}

// ---------------------------------------------------------------------------
// Attention over KV [e][b][1024] (keys 0..511, vals 512..1023); sel fp32.
// Writes actor_in fp32 (d_out) AND bf16 hi/lo planes for the actor GEMM.
// ---------------------------------------------------------------------------
__global__ void attn_kernel(const float* __restrict__ KV, const float* __restrict__ sel,
                            float* __restrict__ actor_in,
                            uint32_t* __restrict__ ain_hi, uint32_t* __restrict__ ain_lo)
{
    const int b = blockIdx.x;
    const int a = threadIdx.x >> 5;
    const int lane = threadIdx.x & 31;
    const int colbase = a * 64 + lane * 2;

    const float2 s2 = *reinterpret_cast<const float2*>(&sel[(long long)b * AD + colbase]);

    float v0[E], v1[E], logit[E];
    #pragma unroll
    for (int e = 0; e < E; ++e) {
        long long off = ((long long)e * Bb + b) * 1024 + colbase;
        float2 k2 = *reinterpret_cast<const float2*>(&KV[off]);
        float2 vv = *reinterpret_cast<const float2*>(&KV[off + 512]);
        v0[e] = vv.x; v1[e] = vv.y;
        float p = s2.x * k2.x + s2.y * k2.y;
        #pragma unroll
        for (int o = 16; o >= 1; o >>= 1) p += __shfl_xor_sync(0xffffffffu, p, o);
        logit[e] = p * 0.125f;
    }
    float mx = logit[0];
    #pragma unroll
    for (int e = 1; e < E; ++e) mx = fmaxf(mx, logit[e]);
    float den = 0.f, w[E];
    #pragma unroll
    for (int e = 0; e < E; ++e) { w[e] = __expf(logit[e] - mx); den += w[e]; }
    float inv = 1.f / den;
    float a0 = 0.f, a1 = 0.f;
    #pragma unroll
    for (int e = 0; e < E; ++e) {
        float we = w[e] * inv;
        a0 += we * v0[e];
        a1 += we * v1[e];
    }
    *reinterpret_cast<float2*>(&actor_in[(long long)b * AD + colbase]) = make_float2(a0, a1);
    uint32_t l; uint32_t h = pack_split(a0, a1, l);
    long long po = (long long)b * 256 + (colbase >> 1);
    ain_hi[po] = h;
    ain_lo[po] = l;
}

// ---------------------------------------------------------------------------
// Launch
// ---------------------------------------------------------------------------
extern "C" void kernel_launch(void* const* d_in, const int* in_sizes, int n_in,
                              void* d_out, int out_size)
{
    float* S = nullptr;
    cudaGetSymbolAddress((void**)&S, g_scratch);
    uint32_t* Su = (uint32_t*)S;

    const float* states      = (const float*)d_in[0];
    const float* pre_actions = (const float*)d_in[1];
    const float* W_enc       = (const float*)d_in[2];
    const float* b_enc       = (const float*)d_in[3];
    const float* W_pre       = (const float*)d_in[4];
    const float* b_pre       = (const float*)d_in[5];
    const float* Wk          = (const float*)d_in[6];
    const float* Wsel        = (const float*)d_in[7];
    const float* Wv          = (const float*)d_in[8];
    const float* bv          = (const float*)d_in[9];
    const float* W_actor     = (const float*)d_in[10];
    const float* b_actor     = (const float*)d_in[11];
    const float* W_mean      = (const float*)d_in[12];
    const float* b_mean      = (const float*)d_in[13];
    const float* W_logstd    = (const float*)d_in[14];
    const float* b_logstd    = (const float*)d_in[15];

    float* out = (float*)d_out;
    float* actor_in = out + 2LL * Bb * 64;   // third output region

    // ---- prep (parallel, tiny) ----
    bn_partial_kernel<<<dim3(16, E), 256>>>(states, S + OFF_SUMS);
    bn_final_kernel<<<2, 256>>>(S + OFF_SUMS, S + OFF_MU, S + OFF_RSTD);
    enc_bias_kernel<<<16, 256>>>(W_enc, b_enc, S + OFF_MU, S + OFF_RSTD, S + OFF_BP);
    enc_split_kernel<<<512, 256>>>(W_enc, S + OFF_RSTD, Su + OFF_EHI, Su + OFF_ELO);
    kv_pack_kernel<<<1024, 256>>>(Wk, Wv, bv, Su + OFF_KVHI, Su + OFF_KVLO, S + OFF_KVB);
    sel_pack_kernel<<<512, 256>>>(Wsel, Su + OFF_SELHI, Su + OFF_SELLO);
    mat_split_kernel<<<512, 256>>>(W_pre, Su + OFF_PREHI, Su + OFF_PRELO);
    mat_split_kernel<<<512, 256>>>(W_actor, Su + OFF_ACTHI, Su + OFF_ACTLO);
    out_pack_kernel<<<128, 256>>>(W_mean, W_logstd, b_mean, b_logstd,
                                  Su + OFF_OHI, Su + OFF_OLO, S + OFF_BOUT);

    // ---- encoder: enc planes = leaky(states @ Wenc' + bp)   A fp32, C planes ----
    mma_gemm_kernel<1, 1, 0><<<dim3(4, 128, E), 256>>>(
        states, nullptr, nullptr, Su + OFF_EHI, Su + OFF_ELO, S + OFF_BP,
        nullptr, Su + OFF_ENCH, Su + OFF_ENCL,
        Bb, H, Nn,
        (long long)Bb * Nn, 512LL * 32, 512LL, (long long)Bb * 256);

    // ---- fused keys|vals: KV = encs @ [Wk|Wv] (+bv, leaky on vals)   A planes, C fp32 ----
    mma_gemm_kernel<3, 0, 1><<<dim3(8, 128, E), 256>>>(
        nullptr, Su + OFF_ENCH, Su + OFF_ENCL, Su + OFF_KVHI, Su + OFF_KVLO, S + OFF_KVB,
        S + OFF_KV, nullptr, nullptr,
        Bb, 1024, H,
        (long long)Bb * 256, 0LL, 0LL, (long long)Bb * 1024);

    // ---- pre planes = leaky(pre_actions @ W_pre + b_pre)   A fp32, C planes ----
    mma_gemm_kernel<1, 1, 0><<<dim3(4, 128, 1), 256>>>(
        pre_actions, nullptr, nullptr, Su + OFF_PREHI, Su + OFF_PRELO, b_pre,
        nullptr, Su + OFF_PREH, Su + OFF_PREL,
        Bb, H, H, 0LL, 0LL, 0LL, 0LL);

    // ---- sel = pre @ Wsel   A planes, C fp32 ----
    mma_gemm_kernel<0, 0, 1><<<dim3(4, 128, 1), 256>>>(
        nullptr, Su + OFF_PREH, Su + OFF_PREL, Su + OFF_SELHI, Su + OFF_SELLO, nullptr,
        S + OFF_SEL, nullptr, nullptr,
        Bb, AD, H, 0LL, 0LL, 0LL, 0LL);

    // ---- attention -> actor_in fp32 (d_out) + planes ----
    attn_kernel<<<Bb, 256>>>(S + OFF_KV, S + OFF_SEL, actor_in,
                             Su + OFF_AINH, Su + OFF_AINL);

    // ---- x planes = relu(actor_in @ W_actor + b_actor)   A planes, C planes ----
    mma_gemm_kernel<2, 1, 1><<<dim3(4, 128, 1), 256>>>(
        nullptr, Su + OFF_AINH, Su + OFF_AINL, Su + OFF_ACTHI, Su + OFF_ACTLO, b_actor,
        nullptr, Su + OFF_XH, Su + OFF_XL,
        Bb, H, H, 0LL, 0LL, 0LL, 0LL);

    // ---- fused output GEMM: [mean | clip(logstd)] -> d_out   A planes ----
    mma_gemm_kernel<4, 0, 1><<<dim3(1, 128, 1), 256>>>(
        nullptr, Su + OFF_XH, Su + OFF_XL, Su + OFF_OHI, Su + OFF_OLO, S + OFF_BOUT,
        out, nullptr, nullptr,
        Bb, 128, H, 0LL, 0LL, 0LL, 0LL);
}

// round 9
// speedup vs baseline: 1.9501x; 1.2614x over previous
#include <cuda_runtime.h>
#include <cuda_bf16.h>
#include <cstdint>

// ---------------------------------------------------------------------------
// Problem constants
// ---------------------------------------------------------------------------
constexpr int E  = 8;
constexpr int Bb = 16384;
constexpr int Nn = 64;
constexpr int H  = 512;
constexpr int AD = 512;            // A*D

// ---------------------------------------------------------------------------
// Scratch layout (4-byte words)
// ---------------------------------------------------------------------------
constexpr long long OFF_SUMS  = 0;                          // 16384
constexpr long long OFF_MU    = OFF_SUMS  + 16384;          // 512
constexpr long long OFF_RSTD  = OFF_MU    + 512;            // 512
constexpr long long OFF_BP    = OFF_RSTD  + 512;            // 4096
constexpr long long OFF_KVB   = OFF_BP    + 4096;           // 1024
constexpr long long OFF_BOUT  = OFF_KVB   + 1024;           // 128
// weight planes
constexpr long long OFF_EHI   = OFF_BOUT  + 128;            // E*512*32 = 131072
constexpr long long OFF_ELO   = OFF_EHI   + 131072;
constexpr long long OFF_KVHI  = OFF_ELO   + 131072;         // 1024*256 = 262144
constexpr long long OFF_KVLO  = OFF_KVHI  + 262144;
constexpr long long OFF_SELHI = OFF_KVLO  + 262144;         // 512*256
constexpr long long OFF_SELLO = OFF_SELHI + 131072;
constexpr long long OFF_PREHI = OFF_SELLO + 131072;
constexpr long long OFF_PRELO = OFF_PREHI + 131072;
constexpr long long OFF_ACTHI = OFF_PRELO + 131072;
constexpr long long OFF_ACTLO = OFF_ACTHI + 131072;
constexpr long long OFF_OHI   = OFF_ACTLO + 131072;         // 128*256
constexpr long long OFF_OLO   = OFF_OHI   + 32768;
// activation planes / buffers
constexpr long long OFF_ENCH  = OFF_OLO   + 32768;          // E*B*256
constexpr long long OFF_ENCL  = OFF_ENCH  + 33554432LL;
constexpr long long OFF_KV    = OFF_ENCL  + 33554432LL;     // E*B*1024 fp32
constexpr long long OFF_PREH  = OFF_KV    + 134217728LL;    // B*256
constexpr long long OFF_PREL  = OFF_PREH  + 4194304LL;
constexpr long long OFF_SEL   = OFF_PREL  + 4194304LL;      // B*512 fp32
constexpr long long OFF_AINH  = OFF_SEL   + 8388608LL;      // B*256
constexpr long long OFF_AINL  = OFF_AINH  + 4194304LL;
constexpr long long OFF_XH    = OFF_AINL  + 4194304LL;      // B*256
constexpr long long OFF_XL    = OFF_XH    + 4194304LL;
constexpr long long SCRATCH_TOTAL = OFF_XL + 4194304LL;     // ~944 MB

__device__ __align__(256) float g_scratch[SCRATCH_TOTAL];

// ---------------------------------------------------------------------------
// Helpers
// ---------------------------------------------------------------------------
__device__ __forceinline__ uint32_t pack_split(float x, float y, uint32_t& lo)
{
    __nv_bfloat16 hx = __float2bfloat16_rn(x);
    __nv_bfloat16 hy = __float2bfloat16_rn(y);
    float rx = x - __bfloat162float(hx);
    float ry = y - __bfloat162float(hy);
    __nv_bfloat16 lx = __float2bfloat16_rn(rx);
    __nv_bfloat16 ly = __float2bfloat16_rn(ry);
    lo = (uint32_t)__bfloat16_as_ushort(lx) | ((uint32_t)__bfloat16_as_ushort(ly) << 16);
    return (uint32_t)__bfloat16_as_ushort(hx) | ((uint32_t)__bfloat16_as_ushort(hy) << 16);
}

#define MMA_BF16(d, a, b0v, b1v)                                              \
    asm volatile("mma.sync.aligned.m16n8k16.row.col.f32.bf16.bf16.f32 "       \
                 "{%0,%1,%2,%3}, {%4,%5,%6,%7}, {%8,%9}, {%0,%1,%2,%3};"      \
                 : "+f"(d[0]), "+f"(d[1]), "+f"(d[2]), "+f"(d[3])             \
                 : "r"(a[0]), "r"(a[1]), "r"(a[2]), "r"(a[3]),                \
                   "r"(b0v), "r"(b1v))

#define LDSM_X4(r, addr)                                                      \
    asm volatile("ldmatrix.sync.aligned.m8n8.x4.shared.b16 {%0,%1,%2,%3}, [%4];" \
                 : "=r"(r[0]), "=r"(r[1]), "=r"(r[2]), "=r"(r[3]) : "r"(addr))

// ---------------------------------------------------------------------------
// BatchNorm stats
// ---------------------------------------------------------------------------
__global__ void bn_partial_kernel(const float* __restrict__ states, float* __restrict__ partial)
{
    int c = blockIdx.x, e = blockIdx.y, t = threadIdx.x;
    int n = t & 63, r0 = t >> 6;
    const float* sp = states + (long long)e * Bb * Nn;
    long long b = (long long)c * 1024 + r0;
    float s1 = 0.f, s2 = 0.f;
    #pragma unroll 4
    for (int it = 0; it < 256; ++it) {
        float v = sp[(b + (long long)it * 4) * Nn + n];
        s1 += v; s2 += v * v;
    }
    __shared__ float sh1[256], sh2[256];
    sh1[t] = s1; sh2[t] = s2;
    __syncthreads();
    if (t < 64) {
        float a1 = sh1[t] + sh1[t + 64] + sh1[t + 128] + sh1[t + 192];
        float a2 = sh2[t] + sh2[t + 64] + sh2[t + 128] + sh2[t + 192];
        long long base = ((long long)e * 16 + c) * 64 + t;
        partial[base] = a1;
        partial[8192 + base] = a2;
    }
}

__global__ void bn_final_kernel(const float* __restrict__ partial,
                                float* __restrict__ mu, float* __restrict__ rstd)
{
    int idx = blockIdx.x * blockDim.x + threadIdx.x;
    if (idx >= E * Nn) return;
    int e = idx >> 6, n = idx & 63;
    float s1 = 0.f, s2 = 0.f;
    for (int c = 0; c < 16; ++c) {
        long long base = ((long long)e * 16 + c) * 64 + n;
        s1 += partial[base];
        s2 += partial[8192 + base];
    }
    float m = s1 * (1.f / Bb);
    float var = s2 * (1.f / Bb) - m * m;
    mu[idx] = m;
    rstd[idx] = rsqrtf(var + 1e-5f);
}

// ---------------------------------------------------------------------------
// Parallel weight-prep kernels
// ---------------------------------------------------------------------------
__global__ void enc_bias_kernel(const float* __restrict__ W_enc, const float* __restrict__ b_enc,
                                const float* __restrict__ mu, const float* __restrict__ rstd,
                                float* __restrict__ bp)
{
    int idx = blockIdx.x * blockDim.x + threadIdx.x;   // e*512+h
    if (idx >= E * H) return;
    int e = idx >> 9, h = idx & 511;
    float bacc = b_enc[idx];
    #pragma unroll 8
    for (int n = 0; n < Nn; ++n)
        bacc -= mu[e * 64 + n] * rstd[e * 64 + n] * W_enc[((long long)e * 64 + n) * H + h];
    bp[idx] = bacc;
}

__global__ void enc_split_kernel(const float* __restrict__ W_enc, const float* __restrict__ rstd,
                                 uint32_t* __restrict__ hi, uint32_t* __restrict__ lo)
{
    int idx = blockIdx.x * blockDim.x + threadIdx.x;   // E*H*32
    if (idx >= E * H * 32) return;
    int h = idx & 511;
    int rest = idx >> 9;
    int p = rest & 31;
    int e = rest >> 5;
    int k = 2 * p;
    float w0 = rstd[e * 64 + k]     * W_enc[((long long)e * 64 + k) * H + h];
    float w1 = rstd[e * 64 + k + 1] * W_enc[((long long)e * 64 + k + 1) * H + h];
    uint32_t l; uint32_t hh = pack_split(w0, w1, l);
    long long o = ((long long)e * 512 + h) * 32 + p;
    hi[o] = hh; lo[o] = l;
}

__global__ void kv_pack_kernel(const float* __restrict__ Wk, const float* __restrict__ Wv,
                               const float* __restrict__ bv,
                               uint32_t* __restrict__ hi, uint32_t* __restrict__ lo,
                               float* __restrict__ kvbias)
{
    int idx = blockIdx.x * blockDim.x + threadIdx.x;   // 1024*256
    if (idx >= 1024 * 256) return;
    int p = idx & 255, n = idx >> 8;
    bool isv = n >= 512;
    int a = (n & 511) >> 6, dd = n & 63;
    const float* W = isv ? Wv : Wk;
    int k = 2 * p;
    float w0 = W[((long long)a * H + k) * 64 + dd];
    float w1 = W[((long long)a * H + k + 1) * 64 + dd];
    uint32_t l; uint32_t hh = pack_split(w0, w1, l);
    hi[idx] = hh; lo[idx] = l;
    if (p == 0) kvbias[n] = isv ? bv[n - 512] : 0.f;
}

__global__ void sel_pack_kernel(const float* __restrict__ Wsel,
                                uint32_t* __restrict__ hi, uint32_t* __restrict__ lo)
{
    int idx = blockIdx.x * blockDim.x + threadIdx.x;   // 512*256
    if (idx >= 512 * 256) return;
    int p = idx & 255, n = idx >> 8;
    int a = n >> 6, dd = n & 63;
    int k = 2 * p;
    float w0 = Wsel[((long long)a * H + k) * 64 + dd];
    float w1 = Wsel[((long long)a * H + k + 1) * 64 + dd];
    uint32_t l; uint32_t hh = pack_split(w0, w1, l);
    hi[idx] = hh; lo[idx] = l;
}

__global__ void mat_split_kernel(const float* __restrict__ W,   // [512][512] k x n
                                 uint32_t* __restrict__ hi, uint32_t* __restrict__ lo)
{
    int idx = blockIdx.x * blockDim.x + threadIdx.x;   // 512*256
    if (idx >= 512 * 256) return;
    int p = idx & 255, n = idx >> 8;
    float w0 = W[(long long)(2 * p) * 512 + n];
    float w1 = W[(long long)(2 * p + 1) * 512 + n];
    uint32_t l; uint32_t hh = pack_split(w0, w1, l);
    hi[idx] = hh; lo[idx] = l;
}

__global__ void out_pack_kernel(const float* __restrict__ W_mean, const float* __restrict__ W_logstd,
                                const float* __restrict__ b_mean, const float* __restrict__ b_logstd,
                                uint32_t* __restrict__ hi, uint32_t* __restrict__ lo,
                                float* __restrict__ bout)
{
    int idx = blockIdx.x * blockDim.x + threadIdx.x;   // 128*256
    if (idx >= 128 * 256) return;
    int p = idx & 255, n = idx >> 8;
    const float* W = (n < 64) ? W_mean : W_logstd;
    int j = n & 63;
    float w0 = W[(long long)(2 * p) * 64 + j];
    float w1 = W[(long long)(2 * p + 1) * 64 + j];
    uint32_t l; uint32_t hh = pack_split(w0, w1, l);
    hi[idx] = hh; lo[idx] = l;
    if (p == 0) bout[n] = (n < 64) ? b_mean[j] : b_logstd[j];
}

// ---------------------------------------------------------------------------
// Split-bf16 tensor-core GEMM, CTA tile 128 x TN, 8 warps x (64 x TN/4).
//   ASRC: 0 = A fp32 (split on the fly), 1 = A pre-split hi/lo planes [M][K/2]
//   ACT : 0 none, 1 leaky, 2 relu, 3 kv-mode (leaky iff col>=512), 4 out-split+clip
//   OUTM: 0 = fp32 C [M][N], 1 = hi/lo planes [M][N/2]
// Double-buffered dynamic smem.
// ---------------------------------------------------------------------------
template <int ACT, int OUTM, int ASRC, int TN>
__global__ __launch_bounds__(256, 1)
void mma_gemm_kernel(const float* __restrict__ Af,
                     const uint32_t* __restrict__ AhiG, const uint32_t* __restrict__ AloG,
                     const uint32_t* __restrict__ BhiG, const uint32_t* __restrict__ BloG,
                     const float* __restrict__ biasg,
                     float* __restrict__ Cf,
                     uint32_t* __restrict__ ChiG, uint32_t* __restrict__ CloG,
                     int M, int N, int K,
                     long long sA, long long sBw, long long sBias, long long sC)
{
    constexpr int ASZ = 128 * 12;          // words per A plane
    constexpr int BSZ = TN * 12;           // words per B plane
    constexpr int BUFW = 2 * ASZ + 2 * BSZ;
    constexpr int WNT = TN / 4;            // warp n-tile (64 or 32)
    constexpr int NJ = WNT / 8;            // n8 tiles per warp
    constexpr int NB = WNT / 16;           // LDSM.x4 per B plane per warp
    constexpr int RB = TN / 128;           // B rows staged per thread

    extern __shared__ uint32_t sm[];

    const int bz = blockIdx.z;
    const float* Ab = (ASRC == 0) ? (Af + bz * sA) : nullptr;
    const uint32_t* AhB = (ASRC == 1) ? (AhiG + bz * sA) : nullptr;
    const uint32_t* AlB = (ASRC == 1) ? (AloG + bz * sA) : nullptr;
    const uint32_t* BhB = BhiG + bz * sBw;
    const uint32_t* BlB = BloG + bz * sBw;
    const float* bias = biasg ? (biasg + bz * sBias) : nullptr;
    float* C = Cf ? (Cf + bz * sC) : nullptr;
    uint32_t* Chi = ChiG ? (ChiG + bz * sC) : nullptr;
    uint32_t* Clo = CloG ? (CloG + bz * sC) : nullptr;

    const int t = threadIdx.x;
    const int lane = t & 31;
    const int warp = t >> 5;
    const int wm = warp >> 2;           // 0..1
    const int wn = warp & 3;            // 0..3
    const int m0 = blockIdx.y * 128;
    const int n0 = blockIdx.x * TN;
    const int Kw = K >> 1;

    // staging roles
    const int am = t >> 1;              // A row 0..127
    const int ak = t & 1;               // A k-half
    const int bpl = t >> 7;             // B plane 0=hi 1=lo
    const int bn0 = (t & 127) * RB;     // B first row

    float acc[4][NJ][4];
    #pragma unroll
    for (int i = 0; i < 4; ++i)
        #pragma unroll
        for (int j = 0; j < NJ; ++j)
            #pragma unroll
            for (int q = 0; q < 4; ++q) acc[i][j][q] = 0.f;

    const uint32_t sbase = (uint32_t)__cvta_generic_to_shared(sm);
    const uint32_t aoff = (((uint32_t)(wm * 64 + (lane & 15)) * 12 + (lane >> 4) * 4)) * 4;
    const uint32_t boff = (((uint32_t)(wn * WNT + (lane & 7) + ((lane >> 4) & 1) * 8) * 12
                            + ((lane >> 3) & 1) * 4)) * 4;

    const float* aptrf = (ASRC == 0) ? (Ab + (long long)(m0 + am) * K + ak * 8) : nullptr;
    const uint32_t* ahptr = (ASRC == 1) ? (AhB + (long long)(m0 + am) * Kw + ak * 4) : nullptr;
    const uint32_t* alptr = (ASRC == 1) ? (AlB + (long long)(m0 + am) * Kw + ak * 4) : nullptr;
    const uint32_t* bptr = (bpl ? BlB : BhB) + (long long)(n0 + bn0) * Kw;

    uint32_t* aS_h = sm + am * 12 + ak * 4;                 // + buf*BUFW
    uint32_t* aS_l = aS_h + ASZ;
    uint32_t* bS = sm + 2 * ASZ + bpl * BSZ + bn0 * 12;

    float4 av0, av1;
    uint4 ahv, alv;
    uint4 bv[RB][2];

    auto load_chunk = [&](int k0) {
        if (ASRC == 0) {
            av0 = *(const float4*)(aptrf + k0);
            av1 = *(const float4*)(aptrf + k0 + 4);
        } else {
            ahv = *(const uint4*)(ahptr + (k0 >> 1));
            alv = *(const uint4*)(alptr + (k0 >> 1));
        }
        #pragma unroll
        for (int r = 0; r < RB; ++r) {
            bv[r][0] = *(const uint4*)(bptr + (long long)r * Kw + (k0 >> 1));
            bv[r][1] = *(const uint4*)(bptr + (long long)r * Kw + (k0 >> 1) + 4);
        }
    };

    auto store_smem = [&](int buf) {
        if (ASRC == 0) {
            float v[8] = {av0.x, av0.y, av0.z, av0.w, av1.x, av1.y, av1.z, av1.w};
            uint32_t hi[4], lo[4];
            #pragma unroll
            for (int j = 0; j < 4; ++j) hi[j] = pack_split(v[2 * j], v[2 * j + 1], lo[j]);
            *(uint4*)(aS_h + buf * BUFW) = make_uint4(hi[0], hi[1], hi[2], hi[3]);
            *(uint4*)(aS_l + buf * BUFW) = make_uint4(lo[0], lo[1], lo[2], lo[3]);
        } else {
            *(uint4*)(aS_h + buf * BUFW) = ahv;
            *(uint4*)(aS_l + buf * BUFW) = alv;
        }
        #pragma unroll
        for (int r = 0; r < RB; ++r) {
            *(uint4*)(bS + buf * BUFW + r * 12) = bv[r][0];
            *(uint4*)(bS + buf * BUFW + r * 12 + 4) = bv[r][1];
        }
    };

    auto mma_step = [&](int buf) {
        const uint32_t b0 = sbase + buf * (BUFW * 4);
        uint32_t AH[4][4], AL[4][4], BH[NB][4], BL[NB][4];
        #pragma unroll
        for (int i = 0; i < 4; ++i) {
            LDSM_X4(AH[i], b0 + aoff + i * (16 * 12 * 4));
            LDSM_X4(AL[i], b0 + ASZ * 4 + aoff + i * (16 * 12 * 4));
        }
        #pragma unroll
        for (int j = 0; j < NB; ++j) {
            LDSM_X4(BH[j], b0 + 2 * ASZ * 4 + boff + j * (16 * 12 * 4));
            LDSM_X4(BL[j], b0 + 2 * ASZ * 4 + BSZ * 4 + boff + j * (16 * 12 * 4));
        }
        #pragma unroll
        for (int i = 0; i < 4; ++i)
            #pragma unroll
            for (int jj = 0; jj < NJ; ++jj) {
                const int jm = jj >> 1, js = (jj & 1) * 2;
                MMA_BF16(acc[i][jj], AH[i], BH[jm][js], BH[jm][js + 1]);
                MMA_BF16(acc[i][jj], AH[i], BL[jm][js], BL[jm][js + 1]);
                MMA_BF16(acc[i][jj], AL[i], BH[jm][js], BH[jm][js + 1]);
            }
    };

    load_chunk(0);
    store_smem(0);
    __syncthreads();

    int buf = 0;
    for (int k0 = 16; k0 < K; k0 += 16) {
        load_chunk(k0);
        mma_step(buf);
        store_smem(buf ^ 1);
        __syncthreads();
        buf ^= 1;
    }
    mma_step(buf);

    // epilogue
    const int g = lane >> 2, tq = lane & 3;
    const int Nw = N >> 1;
    #pragma unroll
    for (int i = 0; i < 4; ++i) {
        const int row = m0 + wm * 64 + i * 16 + g;
        #pragma unroll
        for (int jj = 0; jj < NJ; ++jj) {
            const int col = n0 + wn * WNT + jj * 8 + tq * 2;
            float b0v = bias ? bias[col] : 0.f;
            float b1v = bias ? bias[col + 1] : 0.f;
            float v00 = acc[i][jj][0] + b0v, v01 = acc[i][jj][1] + b1v;
            float v10 = acc[i][jj][2] + b0v, v11 = acc[i][jj][3] + b1v;
            if (ACT == 1) {
                v00 = v00 >= 0.f ? v00 : 0.01f * v00;
                v01 = v01 >= 0.f ? v01 : 0.01f * v01;
                v10 = v10 >= 0.f ? v10 : 0.01f * v10;
                v11 = v11 >= 0.f ? v11 : 0.01f * v11;
            } else if (ACT == 2) {
                v00 = fmaxf(v00, 0.f); v01 = fmaxf(v01, 0.f);
                v10 = fmaxf(v10, 0.f); v11 = fmaxf(v11, 0.f);
            } else if (ACT == 3) {
                if (col >= 512) {
                    v00 = v00 >= 0.f ? v00 : 0.01f * v00;
                    v01 = v01 >= 0.f ? v01 : 0.01f * v01;
                    v10 = v10 >= 0.f ? v10 : 0.01f * v10;
                    v11 = v11 >= 0.f ? v11 : 0.01f * v11;
                }
            }
            if (ACT == 4) {
                const long long base2 = (long long)M * 64;
                float vv[4] = {v00, v01, v10, v11};
                int rr[4] = {row, row, row + 8, row + 8};
                int cc[4] = {col, col + 1, col, col + 1};
                #pragma unroll
                for (int q = 0; q < 4; ++q) {
                    if (cc[q] < 64) {
                        C[(long long)rr[q] * 64 + cc[q]] = vv[q];
                    } else {
                        float x = fminf(fmaxf(vv[q], -20.f), 2.f);
                        C[base2 + (long long)rr[q] * 64 + (cc[q] - 64)] = x;
                    }
                }
            } else if (OUTM == 1) {
                uint32_t l0, l1;
                uint32_t h0 = pack_split(v00, v01, l0);
                uint32_t h1 = pack_split(v10, v11, l1);
                Chi[(long long)row * Nw + (col >> 1)] = h0;
                Clo[(long long)row * Nw + (col >> 1)] = l0;
                Chi[(long long)(row + 8) * Nw + (col >> 1)] = h1;
                Clo[(long long)(row + 8) * Nw + (col >> 1)] = l1;
            } else {
                *(float2*)&C[(long long)row * N + col] = make_float2(v00, v01);
                *(float2*)&C[(long long)(row + 8) * N + col] = make_float2(v10, v11);
            }
        }
    }
}

// ---------------------------------------------------------------------------
// Attention over KV [e][b][1024] (keys 0..511, vals 512..1023); sel fp32.
// Writes actor_in fp32 (d_out) AND bf16 hi/lo planes for the actor GEMM.
// ---------------------------------------------------------------------------
__global__ void attn_kernel(const float* __restrict__ KV, const float* __restrict__ sel,
                            float* __restrict__ actor_in,
                            uint32_t* __restrict__ ain_hi, uint32_t* __restrict__ ain_lo)
{
    const int b = blockIdx.x;
    const int a = threadIdx.x >> 5;
    const int lane = threadIdx.x & 31;
    const int colbase = a * 64 + lane * 2;

    const float2 s2 = *reinterpret_cast<const float2*>(&sel[(long long)b * AD + colbase]);

    float v0[E], v1[E], logit[E];
    #pragma unroll
    for (int e = 0; e < E; ++e) {
        long long off = ((long long)e * Bb + b) * 1024 + colbase;
        float2 k2 = *reinterpret_cast<const float2*>(&KV[off]);
        float2 vv = *reinterpret_cast<const float2*>(&KV[off + 512]);
        v0[e] = vv.x; v1[e] = vv.y;
        float p = s2.x * k2.x + s2.y * k2.y;
        #pragma unroll
        for (int o = 16; o >= 1; o >>= 1) p += __shfl_xor_sync(0xffffffffu, p, o);
        logit[e] = p * 0.125f;
    }
    float mx = logit[0];
    #pragma unroll
    for (int e = 1; e < E; ++e) mx = fmaxf(mx, logit[e]);
    float den = 0.f, w[E];
    #pragma unroll
    for (int e = 0; e < E; ++e) { w[e] = __expf(logit[e] - mx); den += w[e]; }
    float inv = 1.f / den;
    float a0 = 0.f, a1 = 0.f;
    #pragma unroll
    for (int e = 0; e < E; ++e) {
        float we = w[e] * inv;
        a0 += we * v0[e];
        a1 += we * v1[e];
    }
    *reinterpret_cast<float2*>(&actor_in[(long long)b * AD + colbase]) = make_float2(a0, a1);
    uint32_t l; uint32_t h = pack_split(a0, a1, l);
    long long po = (long long)b * 256 + (colbase >> 1);
    ain_hi[po] = h;
    ain_lo[po] = l;
}

// ---------------------------------------------------------------------------
// Launch
// ---------------------------------------------------------------------------
constexpr int SMEM_256 = (2 * 128 * 12 + 2 * 256 * 12) * 2 * 4;   // 73728 B
constexpr int SMEM_128 = (2 * 128 * 12 + 2 * 128 * 12) * 2 * 4;   // 49152 B

extern "C" void kernel_launch(void* const* d_in, const int* in_sizes, int n_in,
                              void* d_out, int out_size)
{
    float* S = nullptr;
    cudaGetSymbolAddress((void**)&S, g_scratch);
    uint32_t* Su = (uint32_t*)S;

    const float* states      = (const float*)d_in[0];
    const float* pre_actions = (const float*)d_in[1];
    const float* W_enc       = (const float*)d_in[2];
    const float* b_enc       = (const float*)d_in[3];
    const float* W_pre       = (const float*)d_in[4];
    const float* b_pre       = (const float*)d_in[5];
    const float* Wk          = (const float*)d_in[6];
    const float* Wsel        = (const float*)d_in[7];
    const float* Wv          = (const float*)d_in[8];
    const float* bv          = (const float*)d_in[9];
    const float* W_actor     = (const float*)d_in[10];
    const float* b_actor     = (const float*)d_in[11];
    const float* W_mean      = (const float*)d_in[12];
    const float* b_mean      = (const float*)d_in[13];
    const float* W_logstd    = (const float*)d_in[14];
    const float* b_logstd    = (const float*)d_in[15];

    float* out = (float*)d_out;
    float* actor_in = out + 2LL * Bb * 64;   // third output region

    // opt-in to >48KB dynamic smem (idempotent; not an allocation)
    cudaFuncSetAttribute(mma_gemm_kernel<1, 1, 0, 256>, cudaFuncAttributeMaxDynamicSharedMemorySize, SMEM_256);
    cudaFuncSetAttribute(mma_gemm_kernel<3, 0, 1, 256>, cudaFuncAttributeMaxDynamicSharedMemorySize, SMEM_256);
    cudaFuncSetAttribute(mma_gemm_kernel<0, 0, 1, 256>, cudaFuncAttributeMaxDynamicSharedMemorySize, SMEM_256);
    cudaFuncSetAttribute(mma_gemm_kernel<2, 1, 1, 256>, cudaFuncAttributeMaxDynamicSharedMemorySize, SMEM_256);
    cudaFuncSetAttribute(mma_gemm_kernel<4, 0, 1, 128>, cudaFuncAttributeMaxDynamicSharedMemorySize, SMEM_128);

    // ---- prep (parallel, tiny) ----
    bn_partial_kernel<<<dim3(16, E), 256>>>(states, S + OFF_SUMS);
    bn_final_kernel<<<2, 256>>>(S + OFF_SUMS, S + OFF_MU, S + OFF_RSTD);
    enc_bias_kernel<<<16, 256>>>(W_enc, b_enc, S + OFF_MU, S + OFF_RSTD, S + OFF_BP);
    enc_split_kernel<<<512, 256>>>(W_enc, S + OFF_RSTD, Su + OFF_EHI, Su + OFF_ELO);
    kv_pack_kernel<<<1024, 256>>>(Wk, Wv, bv, Su + OFF_KVHI, Su + OFF_KVLO, S + OFF_KVB);
    sel_pack_kernel<<<512, 256>>>(Wsel, Su + OFF_SELHI, Su + OFF_SELLO);
    mat_split_kernel<<<512, 256>>>(W_pre, Su + OFF_PREHI, Su + OFF_PRELO);
    mat_split_kernel<<<512, 256>>>(W_actor, Su + OFF_ACTHI, Su + OFF_ACTLO);
    out_pack_kernel<<<128, 256>>>(W_mean, W_logstd, b_mean, b_logstd,
                                  Su + OFF_OHI, Su + OFF_OLO, S + OFF_BOUT);

    // ---- encoder: enc planes = leaky(states @ Wenc' + bp)   A fp32, C planes ----
    mma_gemm_kernel<1, 1, 0, 256><<<dim3(2, 128, E), 256, SMEM_256>>>(
        states, nullptr, nullptr, Su + OFF_EHI, Su + OFF_ELO, S + OFF_BP,
        nullptr, Su + OFF_ENCH, Su + OFF_ENCL,
        Bb, H, Nn,
        (long long)Bb * Nn, 512LL * 32, 512LL, (long long)Bb * 256);

    // ---- fused keys|vals: KV = encs @ [Wk|Wv] (+bv, leaky on vals)   A planes, C fp32 ----
    mma_gemm_kernel<3, 0, 1, 256><<<dim3(4, 128, E), 256, SMEM_256>>>(
        nullptr, Su + OFF_ENCH, Su + OFF_ENCL, Su + OFF_KVHI, Su + OFF_KVLO, S + OFF_KVB,
        S + OFF_KV, nullptr, nullptr,
        Bb, 1024, H,
        (long long)Bb * 256, 0LL, 0LL, (long long)Bb * 1024);

    // ---- pre planes = leaky(pre_actions @ W_pre + b_pre)   A fp32, C planes ----
    mma_gemm_kernel<1, 1, 0, 256><<<dim3(2, 128, 1), 256, SMEM_256>>>(
        pre_actions, nullptr, nullptr, Su + OFF_PREHI, Su + OFF_PRELO, b_pre,
        nullptr, Su + OFF_PREH, Su + OFF_PREL,
        Bb, H, H, 0LL, 0LL, 0LL, 0LL);

    // ---- sel = pre @ Wsel   A planes, C fp32 ----
    mma_gemm_kernel<0, 0, 1, 256><<<dim3(2, 128, 1), 256, SMEM_256>>>(
        nullptr, Su + OFF_PREH, Su + OFF_PREL, Su + OFF_SELHI, Su + OFF_SELLO, nullptr,
        S + OFF_SEL, nullptr, nullptr,
        Bb, AD, H, 0LL, 0LL, 0LL, 0LL);

    // ---- attention -> actor_in fp32 (d_out) + planes ----
    attn_kernel<<<Bb, 256>>>(S + OFF_KV, S + OFF_SEL, actor_in,
                             Su + OFF_AINH, Su + OFF_AINL);

    // ---- x planes = relu(actor_in @ W_actor + b_actor)   A planes, C planes ----
    mma_gemm_kernel<2, 1, 1, 256><<<dim3(2, 128, 1), 256, SMEM_256>>>(
        nullptr, Su + OFF_AINH, Su + OFF_AINL, Su + OFF_ACTHI, Su + OFF_ACTLO, b_actor,
        nullptr, Su + OFF_XH, Su + OFF_XL,
        Bb, H, H, 0LL, 0LL, 0LL, 0LL);

    // ---- fused output GEMM: [mean | clip(logstd)] -> d_out   A planes ----
    mma_gemm_kernel<4, 0, 1, 128><<<dim3(1, 128, 1), 256, SMEM_128>>>(
        nullptr, Su + OFF_XH, Su + OFF_XL, Su + OFF_OHI, Su + OFF_OLO, S + OFF_BOUT,
        out, nullptr, nullptr,
        Bb, 128, H, 0LL, 0LL, 0LL, 0LL);
}